// round 2
// baseline (speedup 1.0000x reference)
#include <cuda_runtime.h>
#include <math.h>

#define N_NODES 50000
#define N_EDGES 800000
#define ET (N_EDGES + N_NODES)
#define HEADS 4
#define OUT_CH 32
#define TOPK 8
#define MAXDEG 128
#define NB_SCAN ((N_NODES + 1023) / 1024)

// ---------------- scratch ----------------
__device__ __align__(16) float g_h[N_NODES * 128];   // 25.6 MB
__device__ __align__(16) float g_si[N_NODES * HEADS];
__device__ __align__(16) float g_sj[N_NODES * HEADS];
__device__ int   g_deg[N_NODES + 1];
__device__ int   g_off[N_NODES + 1];
__device__ int   g_cur[N_NODES];
__device__ int   g_col[ET];
__device__ int   g_bsum[NB_SCAN + 1];

// ---------------- CSR build ----------------
__global__ void k_init() {
    int i = blockIdx.x * blockDim.x + threadIdx.x;
    if (i < N_NODES) { g_deg[i] = 1; g_cur[i] = 0; }   // self-loop counted
}

__global__ void k_hist(const int* __restrict__ ei) {
    int e = blockIdx.x * blockDim.x + threadIdx.x;
    if (e < N_EDGES) atomicAdd(&g_deg[ei[e]], 1);
}

__global__ void k_scan1() {
    __shared__ int sh[1024];
    int tid = threadIdx.x;
    int i = blockIdx.x * 1024 + tid;
    int v = (i < N_NODES) ? g_deg[i] : 0;
    sh[tid] = v;
    __syncthreads();
    #pragma unroll
    for (int o = 1; o < 1024; o <<= 1) {
        int t = (tid >= o) ? sh[tid - o] : 0;
        __syncthreads();
        if (tid >= o) sh[tid] += t;
        __syncthreads();
    }
    if (i < N_NODES) g_off[i] = sh[tid] - v;          // exclusive within block
    if (tid == 1023) g_bsum[blockIdx.x] = sh[1023];   // block total
}

// fused scan2+scan3: each block computes its own carry from block sums
__global__ void k_scan3() {
    __shared__ int carry;
    int tid = threadIdx.x;
    if (tid < 32) {
        int s = 0;
        for (int b = tid; b < blockIdx.x; b += 32) s += g_bsum[b];
        #pragma unroll
        for (int o = 16; o; o >>= 1) s += __shfl_xor_sync(0xffffffffu, s, o);
        if (tid == 0) carry = s;
    }
    __syncthreads();
    int i = blockIdx.x * 1024 + tid;
    if (i < N_NODES) g_off[i] += carry;
    if (i == 0) g_off[N_NODES] = ET;
}

__global__ void k_scatter(const int* __restrict__ ei) {
    int idx = blockIdx.x * blockDim.x + threadIdx.x;
    if (idx >= ET) return;
    int r, c;
    if (idx < N_EDGES) { r = ei[idx]; c = ei[N_EDGES + idx]; }
    else               { r = idx - N_EDGES; c = r; }          // self-loop
    int p = g_off[r] + atomicAdd(&g_cur[r], 1);
    g_col[p] = c;
}

// ---------------- GEMM: h = x @ W, f32x2 packed FMA ------------------------
__device__ __forceinline__ void fma2(unsigned long long& d,
                                     unsigned long long a,
                                     unsigned long long b) {
    asm("fma.rn.f32x2 %0, %1, %2, %0;" : "+l"(d) : "l"(a), "l"(b));
}

__global__ void __launch_bounds__(256, 2)
k_gemm(const float* __restrict__ x, const float* __restrict__ W) {
    __shared__ float Xs[8][132];                 // [k][m], padded
    __shared__ __align__(16) float Ws[8][128];   // [k][n]
    int tid = threadIdx.x;
    int m0 = blockIdx.x * 128;
    int tx = tid & 15;          // col group (8 cols)
    int ty = tid >> 4;          // row group (8 rows)
    int xm = tid >> 1;          // 0..127  X load row
    int xk = (tid & 1) * 4;     // 0 or 4  X load k offset
    int wk = tid >> 5;          // 0..7    W load k
    int wn = (tid & 31) * 4;    // 0..124  W load n

    unsigned long long acc[4][8];
    #pragma unroll
    for (int p = 0; p < 4; p++)
        #pragma unroll
        for (int j = 0; j < 8; j++) acc[p][j] = 0ull;

    for (int kb = 0; kb < 128; kb += 8) {
        float4 xv = make_float4(0.f, 0.f, 0.f, 0.f);
        if (m0 + xm < N_NODES)
            xv = *(const float4*)&x[(m0 + xm) * 128 + kb + xk];
        Xs[xk + 0][xm] = xv.x; Xs[xk + 1][xm] = xv.y;
        Xs[xk + 2][xm] = xv.z; Xs[xk + 3][xm] = xv.w;
        *(float4*)&Ws[wk][wn] = *(const float4*)&W[(kb + wk) * 128 + wn];
        __syncthreads();

        #pragma unroll
        for (int k = 0; k < 8; k++) {
            unsigned long long a[4];
            #pragma unroll
            for (int p = 0; p < 4; p++)
                a[p] = *(const unsigned long long*)&Xs[k][ty * 8 + 2 * p];
            float4 b0 = *(const float4*)&Ws[k][tx * 8];
            float4 b1 = *(const float4*)&Ws[k][tx * 8 + 4];
            unsigned long long B[8];
            asm("mov.b64 %0, {%1, %1};" : "=l"(B[0]) : "f"(b0.x));
            asm("mov.b64 %0, {%1, %1};" : "=l"(B[1]) : "f"(b0.y));
            asm("mov.b64 %0, {%1, %1};" : "=l"(B[2]) : "f"(b0.z));
            asm("mov.b64 %0, {%1, %1};" : "=l"(B[3]) : "f"(b0.w));
            asm("mov.b64 %0, {%1, %1};" : "=l"(B[4]) : "f"(b1.x));
            asm("mov.b64 %0, {%1, %1};" : "=l"(B[5]) : "f"(b1.y));
            asm("mov.b64 %0, {%1, %1};" : "=l"(B[6]) : "f"(b1.z));
            asm("mov.b64 %0, {%1, %1};" : "=l"(B[7]) : "f"(b1.w));
            #pragma unroll
            for (int p = 0; p < 4; p++)
                #pragma unroll
                for (int j = 0; j < 8; j++)
                    fma2(acc[p][j], a[p], B[j]);
        }
        __syncthreads();
    }

    #pragma unroll
    for (int p = 0; p < 4; p++) {
        float2 v[8];
        #pragma unroll
        for (int j = 0; j < 8; j++) v[j] = *reinterpret_cast<float2*>(&acc[p][j]);
        int row0 = m0 + ty * 8 + 2 * p;
        if (row0 < N_NODES) {
            *(float4*)&g_h[row0 * 128 + tx * 8]     = make_float4(v[0].x, v[1].x, v[2].x, v[3].x);
            *(float4*)&g_h[row0 * 128 + tx * 8 + 4] = make_float4(v[4].x, v[5].x, v[6].x, v[7].x);
        }
        int row1 = row0 + 1;
        if (row1 < N_NODES) {
            *(float4*)&g_h[row1 * 128 + tx * 8]     = make_float4(v[0].y, v[1].y, v[2].y, v[3].y);
            *(float4*)&g_h[row1 * 128 + tx * 8 + 4] = make_float4(v[4].y, v[5].y, v[6].y, v[7].y);
        }
    }
}

// ---------------- per-node scores ----------------
__global__ void k_scores(const float* __restrict__ att) {
    int gt = blockIdx.x * blockDim.x + threadIdx.x;
    int w = gt >> 5;
    int lane = gt & 31;
    if (w >= N_NODES) return;
    float4 hv = *(const float4*)&g_h[w * 128 + lane * 4];
    int head = lane >> 3;
    int cbase = (lane & 7) * 4;
    const float* ai = att + head * (2 * OUT_CH) + cbase;
    const float* aj = ai + OUT_CH;
    float pi = hv.x * ai[0] + hv.y * ai[1] + hv.z * ai[2] + hv.w * ai[3];
    float pj = hv.x * aj[0] + hv.y * aj[1] + hv.z * aj[2] + hv.w * aj[3];
    #pragma unroll
    for (int o = 4; o; o >>= 1) {
        pi += __shfl_xor_sync(0xffffffffu, pi, o);
        pj += __shfl_xor_sync(0xffffffffu, pj, o);
    }
    if ((lane & 7) == 0) {
        g_si[w * HEADS + head] = pi;
        g_sj[w * HEADS + head] = pj;
    }
}

// ---------------- top-k + softmax + aggregate + ELU ------------------------
// One warp per node, all 4 heads; edges live in 4 register slots per lane.
__global__ void __launch_bounds__(256) k_agg(float* __restrict__ out) {
    int lane = threadIdx.x & 31;
    int node = (blockIdx.x * blockDim.x + threadIdx.x) >> 5;
    if (node >= N_NODES) return;

    int start = g_off[node];
    int deg = g_off[node + 1] - start;
    int d = min(deg, MAXDEG);
    int k = min(d, TOPK);

    float4 si4 = *(const float4*)&g_si[node * 4];

    int c0 = 0, c1 = 0, c2 = 0, c3 = 0;
    float4 j0, j1, j2, j3;
    j0 = j1 = j2 = j3 = make_float4(-INFINITY, -INFINITY, -INFINITY, -INFINITY);
    if (lane < d)            { c0 = g_col[start + lane];      j0 = *(const float4*)&g_sj[c0 * 4]; }
    if (lane + 32 < d)       { c1 = g_col[start + lane + 32]; j1 = *(const float4*)&g_sj[c1 * 4]; }
    if (lane + 64 < d)       { c2 = g_col[start + lane + 64]; j2 = *(const float4*)&g_sj[c2 * 4]; }
    if (lane + 96 < d)       { c3 = g_col[start + lane + 96]; j3 = *(const float4*)&g_sj[c3 * 4]; }

    #pragma unroll
    for (int h = 0; h < HEADS; h++) {
        float sih = (h == 0) ? si4.x : (h == 1) ? si4.y : (h == 2) ? si4.z : si4.w;
        float s0 = sih + ((h == 0) ? j0.x : (h == 1) ? j0.y : (h == 2) ? j0.z : j0.w);
        float s1 = sih + ((h == 0) ? j1.x : (h == 1) ? j1.y : (h == 2) ? j1.z : j1.w);
        float s2 = sih + ((h == 0) ? j2.x : (h == 1) ? j2.y : (h == 2) ? j2.z : j2.w);
        float s3 = sih + ((h == 0) ? j3.x : (h == 1) ? j3.y : (h == 2) ? j3.z : j3.w);
        s0 = (s0 > 0.f) ? s0 : 0.2f * s0;
        s1 = (s1 > 0.f) ? s1 : 0.2f * s1;
        s2 = (s2 > 0.f) ? s2 : 0.2f * s2;
        s3 = (s3 > 0.f) ? s3 : 0.2f * s3;
        if (lane >= d)      s0 = -INFINITY;
        if (lane + 32 >= d) s1 = -INFINITY;
        if (lane + 64 >= d) s2 = -INFINITY;
        if (lane + 96 >= d) s3 = -INFINITY;

        float ev[TOPK];
        int   cv[TOPK];
        #pragma unroll
        for (int r = 0; r < TOPK; r++) {
            float best = s0; int bi = lane;
            if (s1 > best || (s1 == best && lane + 32 < bi)) { best = s1; bi = lane + 32; }
            if (s2 > best || (s2 == best && lane + 64 < bi)) { best = s2; bi = lane + 64; }
            if (s3 > best || (s3 == best && lane + 96 < bi)) { best = s3; bi = lane + 96; }
            #pragma unroll
            for (int o = 16; o; o >>= 1) {
                float ob = __shfl_xor_sync(0xffffffffu, best, o);
                int   oi = __shfl_xor_sync(0xffffffffu, bi, o);
                if (ob > best || (ob == best && oi < bi)) { best = ob; bi = oi; }
            }
            int wlane = bi & 31;
            int wslot = bi >> 5;
            int mycol = (wslot == 0) ? c0 : (wslot == 1) ? c1 : (wslot == 2) ? c2 : c3;
            int wc = __shfl_sync(0xffffffffu, mycol, wlane);
            ev[r] = best;
            cv[r] = wc;
            if (lane == wlane) {
                if (wslot == 0) s0 = -INFINITY;
                else if (wslot == 1) s1 = -INFINITY;
                else if (wslot == 2) s2 = -INFINITY;
                else s3 = -INFINITY;
            }
        }

        float maxe = ev[0];
        float sum = 0.f, accv = 0.f;
        #pragma unroll
        for (int r = 0; r < TOPK; r++) {
            if (r < k) {
                float p = __expf(ev[r] - maxe);
                sum += p;
                accv += p * __ldg(&g_h[cv[r] * 128 + h * OUT_CH + lane]);
            }
        }
        float o = accv / sum;
        out[node * 128 + h * OUT_CH + lane] = (o > 0.f) ? o : expm1f(o);
    }
}

// ---------------- launch ----------------
extern "C" void kernel_launch(void* const* d_in, const int* in_sizes, int n_in,
                              void* d_out, int out_size) {
    const float* x   = (const float*)d_in[0];
    const float* W   = (const float*)d_in[1];
    const float* att = (const float*)d_in[2];
    const int*   ei  = (const int*)d_in[3];
    float* out = (float*)d_out;

    k_init<<<(N_NODES + 255) / 256, 256>>>();
    k_hist<<<(N_EDGES + 255) / 256, 256>>>(ei);
    k_scan1<<<NB_SCAN, 1024>>>();
    k_scan3<<<NB_SCAN, 1024>>>();
    k_scatter<<<(ET + 255) / 256, 256>>>(ei);
    k_gemm<<<(N_NODES + 127) / 128, 256>>>(x, W);
    k_scores<<<(N_NODES * 32 + 255) / 256, 256>>>(att);
    k_agg<<<(N_NODES * 32 + 255) / 256, 256>>>(out);
}

// round 3
// speedup vs baseline: 1.0004x; 1.0004x over previous
#include <cuda_runtime.h>
#include <math.h>

#define N_NODES 50000
#define N_EDGES 800000
#define ET (N_EDGES + N_NODES)
#define HEADS 4
#define OUT_CH 32
#define TOPK 8
#define MAXDEG 128
#define NB_SCAN ((N_NODES + 1023) / 1024)

// ---------------- scratch ----------------
__device__ __align__(16) float g_h[N_NODES * 128];   // 25.6 MB
__device__ __align__(16) float g_si[N_NODES * HEADS];
__device__ __align__(16) float g_sj[N_NODES * HEADS];
__device__ int   g_deg[N_NODES + 1];
__device__ int   g_off[N_NODES + 1];
__device__ int   g_cur[N_NODES];
__device__ int   g_col[ET];
__device__ int   g_bsum[NB_SCAN + 1];

// ---------------- CSR build ----------------
__global__ void k_init() {
    int i = blockIdx.x * blockDim.x + threadIdx.x;
    if (i < N_NODES) { g_deg[i] = 1; g_cur[i] = 0; }   // self-loop counted
}

__global__ void k_hist(const int* __restrict__ ei) {
    int e = blockIdx.x * blockDim.x + threadIdx.x;
    if (e < N_EDGES) atomicAdd(&g_deg[ei[e]], 1);
}

__global__ void k_scan1() {
    __shared__ int sh[1024];
    int tid = threadIdx.x;
    int i = blockIdx.x * 1024 + tid;
    int v = (i < N_NODES) ? g_deg[i] : 0;
    sh[tid] = v;
    __syncthreads();
    #pragma unroll
    for (int o = 1; o < 1024; o <<= 1) {
        int t = (tid >= o) ? sh[tid - o] : 0;
        __syncthreads();
        if (tid >= o) sh[tid] += t;
        __syncthreads();
    }
    if (i < N_NODES) g_off[i] = sh[tid] - v;          // exclusive within block
    if (tid == 1023) g_bsum[blockIdx.x] = sh[1023];   // block total
}

// fused carry propagation: each block warp-reduces its prefix of block sums
__global__ void k_scan3() {
    __shared__ int carry;
    int tid = threadIdx.x;
    if (tid < 32) {
        int s = 0;
        for (int b = tid; b < blockIdx.x; b += 32) s += g_bsum[b];
        #pragma unroll
        for (int o = 16; o; o >>= 1) s += __shfl_xor_sync(0xffffffffu, s, o);
        if (tid == 0) carry = s;
    }
    __syncthreads();
    int i = blockIdx.x * 1024 + tid;
    if (i < N_NODES) g_off[i] += carry;
    if (i == 0) g_off[N_NODES] = ET;
}

__global__ void k_scatter(const int* __restrict__ ei) {
    int idx = blockIdx.x * blockDim.x + threadIdx.x;
    if (idx >= ET) return;
    int r, c;
    if (idx < N_EDGES) { r = ei[idx]; c = ei[N_EDGES + idx]; }
    else               { r = idx - N_EDGES; c = r; }          // self-loop
    int p = g_off[r] + atomicAdd(&g_cur[r], 1);
    g_col[p] = c;
}

// ---------------- GEMM: h = x @ W, f32x2 FMA, A replicated in smem ---------
__device__ __forceinline__ void fma2(unsigned long long& d,
                                     unsigned long long a,
                                     unsigned long long b) {
    asm("fma.rn.f32x2 %0, %1, %2, %0;" : "+l"(d) : "l"(a), "l"(b));
}

__global__ void __launch_bounds__(256, 2)
k_gemm(const float* __restrict__ x, const float* __restrict__ W) {
    __shared__ __align__(16) float2 Xs2[8][128];   // [k][m] duplicated pair, 8KB
    __shared__ __align__(16) float  Ws[8][128];    // [k][n], 4KB
    int tid = threadIdx.x;
    int m0 = blockIdx.x * 128;
    int tx = tid & 15;          // n group: 8 cols  (4 pairs)
    int ty = tid >> 4;          // m group: 8 rows
    int xm = tid >> 1;          // 0..127  X load row
    int xk = (tid & 1) * 4;     // 0 or 4  X load k offset
    int wk = tid >> 5;          // 0..7    W load k
    int wn = (tid & 31) * 4;    // 0..124  W load n

    // acc[m][np]: packed pair over columns (tx*8 + 2np, tx*8 + 2np + 1)
    unsigned long long acc[8][4];
    #pragma unroll
    for (int m = 0; m < 8; m++)
        #pragma unroll
        for (int p = 0; p < 4; p++) acc[m][p] = 0ull;

    for (int kb = 0; kb < 128; kb += 8) {
        float4 xv = make_float4(0.f, 0.f, 0.f, 0.f);
        if (m0 + xm < N_NODES)
            xv = *(const float4*)&x[(m0 + xm) * 128 + kb + xk];
        Xs2[xk + 0][xm] = make_float2(xv.x, xv.x);
        Xs2[xk + 1][xm] = make_float2(xv.y, xv.y);
        Xs2[xk + 2][xm] = make_float2(xv.z, xv.z);
        Xs2[xk + 3][xm] = make_float2(xv.w, xv.w);
        *(float4*)&Ws[wk][wn] = *(const float4*)&W[(kb + wk) * 128 + wn];
        __syncthreads();

        #pragma unroll
        for (int k = 0; k < 8; k++) {
            const unsigned long long* arow =
                (const unsigned long long*)&Xs2[k][ty * 8];
            ulonglong2 B0 = *(const ulonglong2*)&Ws[k][tx * 8];
            ulonglong2 B1 = *(const ulonglong2*)&Ws[k][tx * 8 + 4];
            #pragma unroll
            for (int m = 0; m < 8; m++) {
                unsigned long long a = arow[m];
                fma2(acc[m][0], a, B0.x);
                fma2(acc[m][1], a, B0.y);
                fma2(acc[m][2], a, B1.x);
                fma2(acc[m][3], a, B1.y);
            }
        }
        __syncthreads();
    }

    #pragma unroll
    for (int m = 0; m < 8; m++) {
        int row = m0 + ty * 8 + m;
        if (row < N_NODES) {
            float2 v0 = *reinterpret_cast<float2*>(&acc[m][0]);
            float2 v1 = *reinterpret_cast<float2*>(&acc[m][1]);
            float2 v2 = *reinterpret_cast<float2*>(&acc[m][2]);
            float2 v3 = *reinterpret_cast<float2*>(&acc[m][3]);
            *(float4*)&g_h[row * 128 + tx * 8]     = make_float4(v0.x, v0.y, v1.x, v1.y);
            *(float4*)&g_h[row * 128 + tx * 8 + 4] = make_float4(v2.x, v2.y, v3.x, v3.y);
        }
    }
}

// ---------------- per-node scores ----------------
__global__ void k_scores(const float* __restrict__ att) {
    int gt = blockIdx.x * blockDim.x + threadIdx.x;
    int w = gt >> 5;
    int lane = gt & 31;
    if (w >= N_NODES) return;
    float4 hv = *(const float4*)&g_h[w * 128 + lane * 4];
    int head = lane >> 3;
    int cbase = (lane & 7) * 4;
    const float* ai = att + head * (2 * OUT_CH) + cbase;
    const float* aj = ai + OUT_CH;
    float pi = hv.x * ai[0] + hv.y * ai[1] + hv.z * ai[2] + hv.w * ai[3];
    float pj = hv.x * aj[0] + hv.y * aj[1] + hv.z * aj[2] + hv.w * aj[3];
    #pragma unroll
    for (int o = 4; o; o >>= 1) {
        pi += __shfl_xor_sync(0xffffffffu, pi, o);
        pj += __shfl_xor_sync(0xffffffffu, pj, o);
    }
    if ((lane & 7) == 0) {
        g_si[w * HEADS + head] = pi;
        g_sj[w * HEADS + head] = pj;
    }
}

// ---------------- top-k + softmax + aggregate + ELU ------------------------
// One warp per (node, head): 200k warps, fully register-resident.
__global__ void __launch_bounds__(256) k_agg(float* __restrict__ out) {
    int lane = threadIdx.x & 31;
    int gw = (blockIdx.x * blockDim.x + threadIdx.x) >> 5;
    if (gw >= N_NODES * HEADS) return;
    int node = gw >> 2;
    int head = gw & 3;

    int start = g_off[node];
    int deg = g_off[node + 1] - start;
    int d = min(deg, MAXDEG);
    int k = min(d, TOPK);
    float si = g_si[node * HEADS + head];

    int c0 = 0, c1 = 0, c2 = 0, c3 = 0;
    float s0 = -INFINITY, s1 = -INFINITY, s2 = -INFINITY, s3 = -INFINITY;
    if (lane < d)      { c0 = g_col[start + lane];      s0 = si + g_sj[c0 * 4 + head]; }
    if (lane + 32 < d) { c1 = g_col[start + lane + 32]; s1 = si + g_sj[c1 * 4 + head]; }
    if (lane + 64 < d) { c2 = g_col[start + lane + 64]; s2 = si + g_sj[c2 * 4 + head]; }
    if (lane + 96 < d) { c3 = g_col[start + lane + 96]; s3 = si + g_sj[c3 * 4 + head]; }
    s0 = (s0 > 0.f) ? s0 : 0.2f * s0;   // leaky(-inf) stays -inf
    s1 = (s1 > 0.f) ? s1 : 0.2f * s1;
    s2 = (s2 > 0.f) ? s2 : 0.2f * s2;
    s3 = (s3 > 0.f) ? s3 : 0.2f * s3;

    float ev[TOPK];
    int   cv[TOPK];
    #pragma unroll
    for (int r = 0; r < TOPK; r++) {
        float best = s0; int bi = lane;
        if (s1 > best) { best = s1; bi = lane + 32; }
        if (s2 > best) { best = s2; bi = lane + 64; }
        if (s3 > best) { best = s3; bi = lane + 96; }
        #pragma unroll
        for (int o = 16; o; o >>= 1) {
            float ob = __shfl_xor_sync(0xffffffffu, best, o);
            int   oi = __shfl_xor_sync(0xffffffffu, bi, o);
            if (ob > best || (ob == best && oi < bi)) { best = ob; bi = oi; }
        }
        int wlane = bi & 31;
        int wslot = bi >> 5;
        int mycol = (wslot == 0) ? c0 : (wslot == 1) ? c1 : (wslot == 2) ? c2 : c3;
        ev[r] = best;
        cv[r] = __shfl_sync(0xffffffffu, mycol, wlane);
        if (lane == wlane) {
            if (wslot == 0) s0 = -INFINITY;
            else if (wslot == 1) s1 = -INFINITY;
            else if (wslot == 2) s2 = -INFINITY;
            else s3 = -INFINITY;
        }
    }

    float maxe = ev[0];
    float sum = 0.f, accv = 0.f;
    #pragma unroll
    for (int r = 0; r < TOPK; r++) {
        if (r < k) {
            float p = __expf(ev[r] - maxe);
            sum += p;
            accv += p * __ldg(&g_h[cv[r] * 128 + head * OUT_CH + lane]);
        }
    }
    float o = accv / sum;
    out[node * 128 + head * OUT_CH + lane] = (o > 0.f) ? o : expm1f(o);
}

// ---------------- launch ----------------
// NOTE: k_gemm deliberately placed at launch slot 3 (the slot ncu captures).
extern "C" void kernel_launch(void* const* d_in, const int* in_sizes, int n_in,
                              void* d_out, int out_size) {
    const float* x   = (const float*)d_in[0];
    const float* W   = (const float*)d_in[1];
    const float* att = (const float*)d_in[2];
    const int*   ei  = (const int*)d_in[3];
    float* out = (float*)d_out;

    k_init<<<(N_NODES + 255) / 256, 256>>>();                       // 0
    k_hist<<<(N_EDGES + 255) / 256, 256>>>(ei);                     // 1
    k_scan1<<<NB_SCAN, 1024>>>();                                   // 2
    k_gemm<<<(N_NODES + 127) / 128, 256>>>(x, W);                   // 3 (profiled)
    k_scan3<<<NB_SCAN, 1024>>>();                                   // 4
    k_scatter<<<(ET + 255) / 256, 256>>>(ei);                       // 5
    k_scores<<<(N_NODES * 32 + 255) / 256, 256>>>(att);             // 6
    k_agg<<<(N_NODES * HEADS * 32 + 255) / 256, 256>>>(out);        // 7
}

// round 4
// speedup vs baseline: 1.7503x; 1.7496x over previous
#include <cuda_runtime.h>
#include <math.h>

#define N_NODES 50000
#define N_EDGES 800000
#define ET (N_EDGES + N_NODES)
#define HEADS 4
#define OUT_CH 32
#define TOPK 8
#define NPAIRS (N_NODES * HEADS)
#define NB_SCAN ((N_NODES + 1023) / 1024)

// ---------------- scratch ----------------
__device__ __align__(16) float g_h[N_NODES * 128];   // 25.6 MB
__device__ __align__(16) float g_si[NPAIRS];
__device__ __align__(16) float g_sj[NPAIRS];
__device__ int   g_deg[N_NODES + 1];
__device__ int   g_off[N_NODES + 1];
__device__ int   g_cur[N_NODES];
__device__ int   g_col[ET];
__device__ int   g_bsum[NB_SCAN + 1];
__device__ __align__(16) float g_ta[NPAIRS * TOPK];  // alphas, 6.4 MB
__device__ __align__(16) int   g_tc[NPAIRS * TOPK];  // columns, 6.4 MB

// ---------------- CSR build ----------------
__global__ void k_init() {
    int i = blockIdx.x * blockDim.x + threadIdx.x;
    if (i < N_NODES) { g_deg[i] = 1; g_cur[i] = 0; }   // self-loop counted
}

__global__ void k_hist(const int* __restrict__ ei) {
    int e = blockIdx.x * blockDim.x + threadIdx.x;
    if (e < N_EDGES) atomicAdd(&g_deg[ei[e]], 1);
}

__global__ void k_scan1() {
    __shared__ int sh[1024];
    int tid = threadIdx.x;
    int i = blockIdx.x * 1024 + tid;
    int v = (i < N_NODES) ? g_deg[i] : 0;
    sh[tid] = v;
    __syncthreads();
    #pragma unroll
    for (int o = 1; o < 1024; o <<= 1) {
        int t = (tid >= o) ? sh[tid - o] : 0;
        __syncthreads();
        if (tid >= o) sh[tid] += t;
        __syncthreads();
    }
    if (i < N_NODES) g_off[i] = sh[tid] - v;          // exclusive within block
    if (tid == 1023) g_bsum[blockIdx.x] = sh[1023];   // block total
}

__global__ void k_scan3() {
    __shared__ int carry;
    int tid = threadIdx.x;
    if (tid < 32) {
        int s = 0;
        for (int b = tid; b < blockIdx.x; b += 32) s += g_bsum[b];
        #pragma unroll
        for (int o = 16; o; o >>= 1) s += __shfl_xor_sync(0xffffffffu, s, o);
        if (tid == 0) carry = s;
    }
    __syncthreads();
    int i = blockIdx.x * 1024 + tid;
    if (i < N_NODES) g_off[i] += carry;
    if (i == 0) g_off[N_NODES] = ET;
}

__global__ void k_scatter(const int* __restrict__ ei) {
    int idx = blockIdx.x * blockDim.x + threadIdx.x;
    if (idx >= ET) return;
    int r, c;
    if (idx < N_EDGES) { r = ei[idx]; c = ei[N_EDGES + idx]; }
    else               { r = idx - N_EDGES; c = r; }          // self-loop
    int p = g_off[r] + atomicAdd(&g_cur[r], 1);
    g_col[p] = c;
}

// ---------------- GEMM: h = x @ W, f32x2 FMA (known: 68us) -----------------
__device__ __forceinline__ void fma2(unsigned long long& d,
                                     unsigned long long a,
                                     unsigned long long b) {
    asm("fma.rn.f32x2 %0, %1, %2, %0;" : "+l"(d) : "l"(a), "l"(b));
}

__global__ void __launch_bounds__(256, 2)
k_gemm(const float* __restrict__ x, const float* __restrict__ W) {
    __shared__ __align__(16) float2 Xs2[8][128];   // [k][m] duplicated pair
    __shared__ __align__(16) float  Ws[8][128];    // [k][n]
    int tid = threadIdx.x;
    int m0 = blockIdx.x * 128;
    int tx = tid & 15;
    int ty = tid >> 4;
    int xm = tid >> 1;
    int xk = (tid & 1) * 4;
    int wk = tid >> 5;
    int wn = (tid & 31) * 4;

    unsigned long long acc[8][4];
    #pragma unroll
    for (int m = 0; m < 8; m++)
        #pragma unroll
        for (int p = 0; p < 4; p++) acc[m][p] = 0ull;

    for (int kb = 0; kb < 128; kb += 8) {
        float4 xv = make_float4(0.f, 0.f, 0.f, 0.f);
        if (m0 + xm < N_NODES)
            xv = *(const float4*)&x[(m0 + xm) * 128 + kb + xk];
        Xs2[xk + 0][xm] = make_float2(xv.x, xv.x);
        Xs2[xk + 1][xm] = make_float2(xv.y, xv.y);
        Xs2[xk + 2][xm] = make_float2(xv.z, xv.z);
        Xs2[xk + 3][xm] = make_float2(xv.w, xv.w);
        *(float4*)&Ws[wk][wn] = *(const float4*)&W[(kb + wk) * 128 + wn];
        __syncthreads();

        #pragma unroll
        for (int k = 0; k < 8; k++) {
            const unsigned long long* arow =
                (const unsigned long long*)&Xs2[k][ty * 8];
            ulonglong2 B0 = *(const ulonglong2*)&Ws[k][tx * 8];
            ulonglong2 B1 = *(const ulonglong2*)&Ws[k][tx * 8 + 4];
            #pragma unroll
            for (int m = 0; m < 8; m++) {
                unsigned long long a = arow[m];
                fma2(acc[m][0], a, B0.x);
                fma2(acc[m][1], a, B0.y);
                fma2(acc[m][2], a, B1.x);
                fma2(acc[m][3], a, B1.y);
            }
        }
        __syncthreads();
    }

    #pragma unroll
    for (int m = 0; m < 8; m++) {
        int row = m0 + ty * 8 + m;
        if (row < N_NODES) {
            float2 v0 = *reinterpret_cast<float2*>(&acc[m][0]);
            float2 v1 = *reinterpret_cast<float2*>(&acc[m][1]);
            float2 v2 = *reinterpret_cast<float2*>(&acc[m][2]);
            float2 v3 = *reinterpret_cast<float2*>(&acc[m][3]);
            *(float4*)&g_h[row * 128 + tx * 8]     = make_float4(v0.x, v0.y, v1.x, v1.y);
            *(float4*)&g_h[row * 128 + tx * 8 + 4] = make_float4(v2.x, v2.y, v3.x, v3.y);
        }
    }
}

// ---------------- per-node scores ----------------
__global__ void k_scores(const float* __restrict__ att) {
    int gt = blockIdx.x * blockDim.x + threadIdx.x;
    int w = gt >> 5;
    int lane = gt & 31;
    if (w >= N_NODES) return;
    float4 hv = *(const float4*)&g_h[w * 128 + lane * 4];
    int head = lane >> 3;
    int cbase = (lane & 7) * 4;
    const float* ai = att + head * (2 * OUT_CH) + cbase;
    const float* aj = ai + OUT_CH;
    float pi = hv.x * ai[0] + hv.y * ai[1] + hv.z * ai[2] + hv.w * ai[3];
    float pj = hv.x * aj[0] + hv.y * aj[1] + hv.z * aj[2] + hv.w * aj[3];
    #pragma unroll
    for (int o = 4; o; o >>= 1) {
        pi += __shfl_xor_sync(0xffffffffu, pi, o);
        pj += __shfl_xor_sync(0xffffffffu, pj, o);
    }
    if ((lane & 7) == 0) {
        g_si[w * HEADS + head] = pi;
        g_sj[w * HEADS + head] = pj;
    }
}

// ---------------- top-k: one THREAD per (node, head), register insertion ----
__global__ void __launch_bounds__(256) k_topk() {
    int t = blockIdx.x * blockDim.x + threadIdx.x;
    if (t >= NPAIRS) return;
    int node = t >> 2;
    int head = t & 3;

    int start = g_off[node];
    int end   = g_off[node + 1];
    float si = g_si[node * HEADS + head];

    unsigned long long top[TOPK];   // key = mono(score)<<32 | col, desc sorted
    #pragma unroll
    for (int r = 0; r < TOPK; r++) top[r] = 0ull;  // 0 < mono(-inf), safe floor

    for (int i = start; i < end; i++) {
        int c = __ldg(&g_col[i]);
        float s = si + __ldg(&g_sj[c * HEADS + head]);
        s = (s > 0.f) ? s : 0.2f * s;                        // leaky_relu(0.2)
        unsigned u = __float_as_uint(s);
        u ^= (unsigned)((int)u >> 31) | 0x80000000u;         // monotone map
        unsigned long long key = ((unsigned long long)u << 32) | (unsigned)c;
        if (key > top[TOPK - 1]) {
            top[TOPK - 1] = key;
            #pragma unroll
            for (int r = TOPK - 1; r > 0; r--) {
                unsigned long long a = top[r - 1], b = top[r];
                top[r - 1] = (b > a) ? b : a;
                top[r]     = (b > a) ? a : b;
            }
        }
    }

    int deg = end - start;
    int k = min(deg, TOPK);
    // scores back to float
    float sc[TOPK];
    #pragma unroll
    for (int r = 0; r < TOPK; r++) {
        unsigned u = (unsigned)(top[r] >> 32);
        u ^= (~((unsigned)((int)u >> 31))) | 0x80000000u;    // inverse map
        sc[r] = __uint_as_float(u);
    }
    float maxe = sc[0];
    float p[TOPK];
    float sum = 0.f;
    #pragma unroll
    for (int r = 0; r < TOPK; r++) {
        float e = (r < k) ? __expf(sc[r] - maxe) : 0.f;
        p[r] = e;
        sum += e;
    }
    float inv = 1.f / sum;
    #pragma unroll
    for (int r = 0; r < TOPK; r++) {
        g_ta[t * TOPK + r] = p[r] * inv;
        g_tc[t * TOPK + r] = (int)(unsigned)(top[r] & 0xffffffffull);
    }
}

// ---------------- aggregate: one warp per (node, head), pure gather --------
__global__ void __launch_bounds__(256) k_aggB(float* __restrict__ out) {
    int lane = threadIdx.x & 31;
    int gw = (blockIdx.x * blockDim.x + threadIdx.x) >> 5;
    if (gw >= NPAIRS) return;
    int node = gw >> 2;
    int head = gw & 3;

    float a[TOPK];
    int   c[TOPK];
    #pragma unroll
    for (int r = 0; r < TOPK; r++) {
        a[r] = g_ta[gw * TOPK + r];       // broadcast loads
        c[r] = g_tc[gw * TOPK + r];
    }
    float acc = 0.f;
    #pragma unroll
    for (int r = 0; r < TOPK; r++)
        acc += a[r] * __ldg(&g_h[c[r] * 128 + head * OUT_CH + lane]);

    out[node * 128 + head * OUT_CH + lane] = (acc > 0.f) ? acc : expm1f(acc);
}

// ---------------- launch (slot 3 = k_hist for ncu) --------------------------
extern "C" void kernel_launch(void* const* d_in, const int* in_sizes, int n_in,
                              void* d_out, int out_size) {
    const float* x   = (const float*)d_in[0];
    const float* W   = (const float*)d_in[1];
    const float* att = (const float*)d_in[2];
    const int*   ei  = (const int*)d_in[3];
    float* out = (float*)d_out;

    k_gemm<<<(N_NODES + 127) / 128, 256>>>(x, W);                   // 0
    k_scores<<<(N_NODES * 32 + 255) / 256, 256>>>(att);             // 1
    k_init<<<(N_NODES + 255) / 256, 256>>>();                       // 2
    k_hist<<<(N_EDGES + 255) / 256, 256>>>(ei);                     // 3 (profiled)
    k_scan1<<<NB_SCAN, 1024>>>();                                   // 4
    k_scan3<<<NB_SCAN, 1024>>>();                                   // 5
    k_scatter<<<(ET + 255) / 256, 256>>>(ei);                       // 6
    k_topk<<<(NPAIRS + 255) / 256, 256>>>();                        // 7
    k_aggB<<<(NPAIRS * 32 + 255) / 256, 256>>>(out);                // 8
}

// round 6
// speedup vs baseline: 1.9592x; 1.1194x over previous
#include <cuda_runtime.h>
#include <cuda_bf16.h>
#include <math.h>
#include <stdint.h>

#define N_NODES 50000
#define N_EDGES 800000
#define ET (N_EDGES + N_NODES)
#define HEADS 4
#define OUT_CH 32
#define TOPK 8
#define NPAIRS (N_NODES * HEADS)
#define NB_SCAN ((N_NODES + 1023) / 1024)

// ---------------- scratch ----------------
__device__ __align__(16) float g_h[N_NODES * 128];           // 25.6 MB
__device__ __align__(16) float g_si[NPAIRS];
__device__ __align__(16) float g_sj[NPAIRS];
__device__ int   g_deg[N_NODES + 1];
__device__ int   g_off[N_NODES + 1];
__device__ int   g_cur[N_NODES];
__device__ int   g_col[ET];
__device__ int   g_bsum[NB_SCAN + 1];
__device__ __align__(16) float g_ta[NPAIRS * TOPK];
__device__ __align__(16) int   g_tc[NPAIRS * TOPK];
__device__ __align__(16) __nv_bfloat16 g_wth[128 * 128];     // W^T hi [n][k]
__device__ __align__(16) __nv_bfloat16 g_wtl[128 * 128];     // W^T lo [n][k]
__device__ __align__(16) float g_a2[128 * 8];                // W @ att combos

// ---------------- prep: W^T split to bf16 + A2 ------------------------------
__global__ void k_prep(const float* __restrict__ W, const float* __restrict__ att) {
    int t = blockIdx.x * blockDim.x + threadIdx.x;
    if (t < 16384) {
        int n = t >> 7, k = t & 127;
        float w = W[k * 128 + n];
        __nv_bfloat16 hi = __float2bfloat16(w);
        float lo = w - __bfloat162float(hi);
        g_wth[n * 128 + k] = hi;
        g_wtl[n * 128 + k] = __float2bfloat16(lo);
    }
    if (t < 1024) {
        int k = t >> 3, j = t & 7;
        int h = j & 3, part = j >> 2;           // part 0: a_i, part 1: a_j
        float s = 0.f;
        #pragma unroll
        for (int c = 0; c < 32; c++)
            s += W[k * 128 + h * 32 + c] * att[h * 64 + part * 32 + c];
        g_a2[k * 8 + j] = s;
    }
}

// ---------------- CSR build ----------------
__global__ void k_init() {
    int i = blockIdx.x * blockDim.x + threadIdx.x;
    if (i < N_NODES) { g_deg[i] = 1; g_cur[i] = 0; }
}

__global__ void k_hist(const int* __restrict__ ei) {
    int e = blockIdx.x * blockDim.x + threadIdx.x;
    if (e < N_EDGES) atomicAdd(&g_deg[ei[e]], 1);
}

__global__ void k_scan1() {
    __shared__ int sh[1024];
    int tid = threadIdx.x;
    int i = blockIdx.x * 1024 + tid;
    int v = (i < N_NODES) ? g_deg[i] : 0;
    sh[tid] = v;
    __syncthreads();
    #pragma unroll
    for (int o = 1; o < 1024; o <<= 1) {
        int t = (tid >= o) ? sh[tid - o] : 0;
        __syncthreads();
        if (tid >= o) sh[tid] += t;
        __syncthreads();
    }
    if (i < N_NODES) g_off[i] = sh[tid] - v;
    if (tid == 1023) g_bsum[blockIdx.x] = sh[1023];
}

__global__ void k_scan3() {
    __shared__ int carry;
    int tid = threadIdx.x;
    if (tid < 32) {
        int s = 0;
        for (int b = tid; b < blockIdx.x; b += 32) s += g_bsum[b];
        #pragma unroll
        for (int o = 16; o; o >>= 1) s += __shfl_xor_sync(0xffffffffu, s, o);
        if (tid == 0) carry = s;
    }
    __syncthreads();
    int i = blockIdx.x * 1024 + tid;
    if (i < N_NODES) g_off[i] += carry;
    if (i == 0) g_off[N_NODES] = ET;
}

__global__ void k_scatter(const int* __restrict__ ei) {
    int idx = blockIdx.x * blockDim.x + threadIdx.x;
    if (idx >= ET) return;
    int r, c;
    if (idx < N_EDGES) { r = ei[idx]; c = ei[N_EDGES + idx]; }
    else               { r = idx - N_EDGES; c = r; }
    int p = g_off[r] + atomicAdd(&g_cur[r], 1);
    g_col[p] = c;
}

// ---------------- GEMM: h = x @ W via mma.sync bf16, 3-term split ----------
#define KP 40   // padded k stride (bf16 elems): 80B rows -> conflict-free frags

__device__ __forceinline__ void hmma(float* c, const uint32_t* a,
                                     uint32_t b0, uint32_t b1) {
    asm volatile(
        "mma.sync.aligned.m16n8k16.row.col.f32.bf16.bf16.f32 "
        "{%0,%1,%2,%3}, {%4,%5,%6,%7}, {%8,%9}, {%0,%1,%2,%3};"
        : "+f"(c[0]), "+f"(c[1]), "+f"(c[2]), "+f"(c[3])
        : "r"(a[0]), "r"(a[1]), "r"(a[2]), "r"(a[3]), "r"(b0), "r"(b1));
}

__global__ void __launch_bounds__(256)
k_gemm(const float* __restrict__ x) {
    __shared__ __nv_bfloat16 sAh[128][KP];
    __shared__ __nv_bfloat16 sAl[128][KP];
    __shared__ __nv_bfloat16 sBh[128][KP];
    __shared__ __nv_bfloat16 sBl[128][KP];

    int tid = threadIdx.x;
    int wid = tid >> 5, lane = tid & 31;
    int m0 = blockIdx.x * 128;
    int rb = (wid & 3) * 32;      // warp row base (M)
    int nb = (wid >> 2) * 64;     // warp col base (N)

    float acc[2][8][4];
    #pragma unroll
    for (int mt = 0; mt < 2; mt++)
        #pragma unroll
        for (int nt = 0; nt < 8; nt++)
            #pragma unroll
            for (int q = 0; q < 4; q++) acc[mt][nt][q] = 0.f;

    for (int st = 0; st < 4; st++) {
        int k0 = st * 32;
        // ---- fill A (x tile, split hi/lo): 128 rows x 32 cols
        #pragma unroll
        for (int it = 0; it < 2; it++) {
            int idx = tid + it * 256;           // 0..511
            int row = idx >> 2;
            int c0 = (idx & 3) * 8;
            float4 v0 = make_float4(0.f, 0.f, 0.f, 0.f), v1 = v0;
            int rr = m0 + row;
            if (rr < N_NODES) {
                v0 = *(const float4*)&x[rr * 128 + k0 + c0];
                v1 = *(const float4*)&x[rr * 128 + k0 + c0 + 4];
            }
            float vs[8] = {v0.x, v0.y, v0.z, v0.w, v1.x, v1.y, v1.z, v1.w};
            uint32_t hw[4], lw[4];
            #pragma unroll
            for (int q = 0; q < 4; q++) {
                __nv_bfloat16 h0 = __float2bfloat16(vs[2 * q]);
                __nv_bfloat16 h1 = __float2bfloat16(vs[2 * q + 1]);
                float l0 = vs[2 * q] - __bfloat162float(h0);
                float l1 = vs[2 * q + 1] - __bfloat162float(h1);
                hw[q] = (uint32_t)__bfloat16_as_ushort(h0) |
                        ((uint32_t)__bfloat16_as_ushort(h1) << 16);
                lw[q] = (uint32_t)__bfloat16_as_ushort(__float2bfloat16(l0)) |
                        ((uint32_t)__bfloat16_as_ushort(__float2bfloat16(l1)) << 16);
            }
            *(uint4*)&sAh[row][c0] = make_uint4(hw[0], hw[1], hw[2], hw[3]);
            *(uint4*)&sAl[row][c0] = make_uint4(lw[0], lw[1], lw[2], lw[3]);
        }
        // ---- fill B (W^T tile, pre-split): 128 n x 32 k
        #pragma unroll
        for (int it = 0; it < 2; it++) {
            int idx = tid + it * 256;
            int n = idx >> 2;
            int c0 = (idx & 3) * 8;
            *(uint4*)&sBh[n][c0] = *(const uint4*)&g_wth[n * 128 + k0 + c0];
            *(uint4*)&sBl[n][c0] = *(const uint4*)&g_wtl[n * 128 + k0 + c0];
        }
        __syncthreads();

        #pragma unroll
        for (int ks = 0; ks < 2; ks++) {
            int c = ks * 16 + (lane & 3) * 2;
            uint32_t Ah[2][4], Al[2][4];
            #pragma unroll
            for (int mt = 0; mt < 2; mt++) {
                int r = rb + mt * 16 + (lane >> 2);
                Ah[mt][0] = *(const uint32_t*)&sAh[r][c];
                Ah[mt][1] = *(const uint32_t*)&sAh[r + 8][c];
                Ah[mt][2] = *(const uint32_t*)&sAh[r][c + 8];
                Ah[mt][3] = *(const uint32_t*)&sAh[r + 8][c + 8];
                Al[mt][0] = *(const uint32_t*)&sAl[r][c];
                Al[mt][1] = *(const uint32_t*)&sAl[r + 8][c];
                Al[mt][2] = *(const uint32_t*)&sAl[r][c + 8];
                Al[mt][3] = *(const uint32_t*)&sAl[r + 8][c + 8];
            }
            #pragma unroll
            for (int nt = 0; nt < 8; nt++) {
                int n = nb + nt * 8 + (lane >> 2);
                uint32_t bh0 = *(const uint32_t*)&sBh[n][c];
                uint32_t bh1 = *(const uint32_t*)&sBh[n][c + 8];
                uint32_t bl0 = *(const uint32_t*)&sBl[n][c];
                uint32_t bl1 = *(const uint32_t*)&sBl[n][c + 8];
                #pragma unroll
                for (int mt = 0; mt < 2; mt++) {
                    hmma(acc[mt][nt], Ah[mt], bh0, bh1);
                    hmma(acc[mt][nt], Ah[mt], bl0, bl1);
                    hmma(acc[mt][nt], Al[mt], bh0, bh1);
                }
            }
        }
        __syncthreads();
    }

    // ---- epilogue
    #pragma unroll
    for (int mt = 0; mt < 2; mt++) {
        int r0 = m0 + rb + mt * 16 + (lane >> 2);
        #pragma unroll
        for (int nt = 0; nt < 8; nt++) {
            int col = nb + nt * 8 + (lane & 3) * 2;
            if (r0 < N_NODES)
                *(float2*)&g_h[r0 * 128 + col] =
                    make_float2(acc[mt][nt][0], acc[mt][nt][1]);
            if (r0 + 8 < N_NODES)
                *(float2*)&g_h[(r0 + 8) * 128 + col] =
                    make_float2(acc[mt][nt][2], acc[mt][nt][3]);
        }
    }
}

// ---------------- scores from x directly (exact fp32): s = x @ A2 ----------
__global__ void k_scores(const float* __restrict__ x) {
    __shared__ float A2T[8 * 128];
    int tid = threadIdx.x;
    for (int i = tid; i < 1024; i += 256) {
        int j = i >> 7, k = i & 127;
        A2T[i] = g_a2[k * 8 + j];
    }
    __syncthreads();
    int lane = tid & 31;
    int node = (blockIdx.x * 256 + tid) >> 5;
    if (node >= N_NODES) return;
    float4 xv = *(const float4*)&x[node * 128 + lane * 4];
    float r[8];
    #pragma unroll
    for (int j = 0; j < 8; j++) {
        float4 a = *(const float4*)&A2T[j * 128 + lane * 4];
        r[j] = xv.x * a.x + xv.y * a.y + xv.z * a.z + xv.w * a.w;
    }
    #pragma unroll
    for (int o = 16; o; o >>= 1)
        #pragma unroll
        for (int j = 0; j < 8; j++)
            r[j] += __shfl_xor_sync(0xffffffffu, r[j], o);
    if (lane < 8) {
        float v = (lane == 0) ? r[0] : (lane == 1) ? r[1] : (lane == 2) ? r[2] :
                  (lane == 3) ? r[3] : (lane == 4) ? r[4] : (lane == 5) ? r[5] :
                  (lane == 6) ? r[6] : r[7];
        int h = lane & 3;
        if (lane < 4) g_si[node * 4 + h] = v;
        else          g_sj[node * 4 + h] = v;
    }
}

// ---------------- top-k: one thread per (node, head) ------------------------
__global__ void __launch_bounds__(256) k_topk() {
    int t = blockIdx.x * blockDim.x + threadIdx.x;
    if (t >= NPAIRS) return;
    int node = t >> 2;
    int head = t & 3;

    int start = g_off[node];
    int end   = g_off[node + 1];
    float si = g_si[node * HEADS + head];

    unsigned long long top[TOPK];
    #pragma unroll
    for (int r = 0; r < TOPK; r++) top[r] = 0ull;

    for (int i = start; i < end; i++) {
        int c = __ldg(&g_col[i]);
        float s = si + __ldg(&g_sj[c * HEADS + head]);
        s = (s > 0.f) ? s : 0.2f * s;
        unsigned u = __float_as_uint(s);
        u ^= (unsigned)((int)u >> 31) | 0x80000000u;
        unsigned long long key = ((unsigned long long)u << 32) | (unsigned)c;
        if (key > top[TOPK - 1]) {
            top[TOPK - 1] = key;
            #pragma unroll
            for (int r = TOPK - 1; r > 0; r--) {
                unsigned long long a = top[r - 1], b = top[r];
                top[r - 1] = (b > a) ? b : a;
                top[r]     = (b > a) ? a : b;
            }
        }
    }

    int deg = end - start;
    int k = min(deg, TOPK);
    float sc[TOPK];
    #pragma unroll
    for (int r = 0; r < TOPK; r++) {
        unsigned u = (unsigned)(top[r] >> 32);
        u ^= (~((unsigned)((int)u >> 31))) | 0x80000000u;
        sc[r] = __uint_as_float(u);
    }
    float maxe = sc[0];
    float p[TOPK];
    float sum = 0.f;
    #pragma unroll
    for (int r = 0; r < TOPK; r++) {
        float e = (r < k) ? __expf(sc[r] - maxe) : 0.f;
        p[r] = e;
        sum += e;
    }
    float inv = 1.f / sum;
    #pragma unroll
    for (int r = 0; r < TOPK; r++) {
        g_ta[t * TOPK + r] = p[r] * inv;
        g_tc[t * TOPK + r] = (int)(unsigned)(top[r] & 0xffffffffull);
    }
}

// ---------------- aggregate: one warp per (node, head) ----------------------
__global__ void __launch_bounds__(256) k_aggB(float* __restrict__ out) {
    int lane = threadIdx.x & 31;
    int gw = (blockIdx.x * blockDim.x + threadIdx.x) >> 5;
    if (gw >= NPAIRS) return;
    int node = gw >> 2;
    int head = gw & 3;

    float a[TOPK];
    int   c[TOPK];
    #pragma unroll
    for (int r = 0; r < TOPK; r++) {
        a[r] = g_ta[gw * TOPK + r];
        c[r] = g_tc[gw * TOPK + r];
    }
    float acc = 0.f;
    #pragma unroll
    for (int r = 0; r < TOPK; r++)
        acc += a[r] * __ldg(&g_h[c[r] * 128 + head * OUT_CH + lane]);

    out[node * 128 + head * OUT_CH + lane] = (acc > 0.f) ? acc : expm1f(acc);
}

// ---------------- launch (slot 3 = k_gemm for ncu) --------------------------
extern "C" void kernel_launch(void* const* d_in, const int* in_sizes, int n_in,
                              void* d_out, int out_size) {
    const float* x   = (const float*)d_in[0];
    const float* W   = (const float*)d_in[1];
    const float* att = (const float*)d_in[2];
    const int*   ei  = (const int*)d_in[3];
    float* out = (float*)d_out;

    k_prep<<<64, 256>>>(W, att);                                    // 0
    k_init<<<(N_NODES + 255) / 256, 256>>>();                       // 1
    k_hist<<<(N_EDGES + 255) / 256, 256>>>(ei);                     // 2
    k_gemm<<<(N_NODES + 127) / 128, 256>>>(x);                      // 3 (profiled)
    k_scores<<<(N_NODES * 32 + 255) / 256, 256>>>(x);               // 4
    k_scan1<<<NB_SCAN, 1024>>>();                                   // 5
    k_scan3<<<NB_SCAN, 1024>>>();                                   // 6
    k_scatter<<<(ET + 255) / 256, 256>>>(ei);                       // 7
    k_topk<<<(NPAIRS + 255) / 256, 256>>>();                        // 8
    k_aggB<<<(NPAIRS * 32 + 255) / 256, 256>>>(out);                // 9
}

// round 7
// speedup vs baseline: 1.9884x; 1.0149x over previous
#include <cuda_runtime.h>
#include <cuda_bf16.h>
#include <math.h>
#include <stdint.h>

#define N_NODES 50000
#define N_EDGES 800000
#define ET (N_EDGES + N_NODES)
#define HEADS 4
#define OUT_CH 32
#define TOPK 8
#define NPAIRS (N_NODES * HEADS)
#define NB_SCAN ((N_NODES + 1023) / 1024)

// ---------------- scratch ----------------
__device__ __align__(16) float g_h[N_NODES * 128];           // 25.6 MB
__device__ __align__(16) __nv_bfloat16 g_xh[N_NODES * 128];  // 12.8 MB
__device__ __align__(16) __nv_bfloat16 g_xl[N_NODES * 128];  // 12.8 MB
__device__ __align__(16) float g_si[NPAIRS];
__device__ __align__(16) float g_sj[NPAIRS];
__device__ int   g_deg[N_NODES + 1];     // .bss zero; reset by scan1 each run
__device__ int   g_off[N_NODES + 1];
__device__ int   g_cur[N_NODES];
__device__ int   g_col[ET];
__device__ int   g_bsum[NB_SCAN + 1];
__device__ __align__(16) float g_ta[NPAIRS * TOPK];
__device__ __align__(16) int   g_tc[NPAIRS * TOPK];
__device__ __align__(16) __nv_bfloat16 g_wth[128 * 128];     // W^T hi [n][k]
__device__ __align__(16) __nv_bfloat16 g_wtl[128 * 128];     // W^T lo [n][k]
__device__ __align__(16) float g_a2[128 * 8];                // W @ att combos

// ---------------- prep: W^T split to bf16 + A2 ------------------------------
__global__ void k_prep(const float* __restrict__ W, const float* __restrict__ att) {
    int t = blockIdx.x * blockDim.x + threadIdx.x;
    if (t < 16384) {
        int n = t >> 7, k = t & 127;
        float w = W[k * 128 + n];
        __nv_bfloat16 hi = __float2bfloat16(w);
        float lo = w - __bfloat162float(hi);
        g_wth[n * 128 + k] = hi;
        g_wtl[n * 128 + k] = __float2bfloat16(lo);
    }
    if (t < 1024) {
        int k = t >> 3, j = t & 7;
        int h = j & 3, part = j >> 2;           // part 0: a_i, part 1: a_j
        float s = 0.f;
        #pragma unroll
        for (int c = 0; c < 32; c++)
            s += W[k * 128 + h * 32 + c] * att[h * 64 + part * 32 + c];
        g_a2[k * 8 + j] = s;
    }
}

// ---------------- CSR build ----------------
__global__ void k_hist(const int* __restrict__ ei) {
    int e = (blockIdx.x * blockDim.x + threadIdx.x) * 4;
    if (e < N_EDGES) {
        int4 v = *(const int4*)&ei[e];
        atomicAdd(&g_deg[v.x], 1);
        atomicAdd(&g_deg[v.y], 1);
        atomicAdd(&g_deg[v.z], 1);
        atomicAdd(&g_deg[v.w], 1);
    }
}

__global__ void k_scan1() {
    __shared__ int sh[1024];
    int tid = threadIdx.x;
    int i = blockIdx.x * 1024 + tid;
    int v = 0;
    if (i < N_NODES) {
        v = g_deg[i] + 1;       // +1 self-loop
        g_deg[i] = 0;           // reset for next graph replay
        g_cur[i] = 0;
    }
    sh[tid] = v;
    __syncthreads();
    #pragma unroll
    for (int o = 1; o < 1024; o <<= 1) {
        int t = (tid >= o) ? sh[tid - o] : 0;
        __syncthreads();
        if (tid >= o) sh[tid] += t;
        __syncthreads();
    }
    if (i < N_NODES) g_off[i] = sh[tid] - v;
    if (tid == 1023) g_bsum[blockIdx.x] = sh[1023];
}

__global__ void k_scan3() {
    __shared__ int carry;
    int tid = threadIdx.x;
    if (tid < 32) {
        int s = 0;
        for (int b = tid; b < blockIdx.x; b += 32) s += g_bsum[b];
        #pragma unroll
        for (int o = 16; o; o >>= 1) s += __shfl_xor_sync(0xffffffffu, s, o);
        if (tid == 0) carry = s;
    }
    __syncthreads();
    int i = blockIdx.x * 1024 + tid;
    if (i < N_NODES) g_off[i] += carry;
    if (i == 0) g_off[N_NODES] = ET;
}

__global__ void k_scatter(const int* __restrict__ ei) {
    int idx = blockIdx.x * blockDim.x + threadIdx.x;
    if (idx >= ET) return;
    int r, c;
    if (idx < N_EDGES) { r = ei[idx]; c = ei[N_EDGES + idx]; }
    else               { r = idx - N_EDGES; c = r; }
    int p = g_off[r] + atomicAdd(&g_cur[r], 1);
    g_col[p] = c;
}

// ---------------- scores + bf16 split of x ----------------------------------
__global__ void k_scores(const float* __restrict__ x) {
    __shared__ float A2T[8 * 128];
    int tid = threadIdx.x;
    for (int i = tid; i < 1024; i += 256) {
        int j = i >> 7, k = i & 127;
        A2T[i] = g_a2[k * 8 + j];
    }
    __syncthreads();
    int lane = tid & 31;
    int node = (blockIdx.x * 256 + tid) >> 5;
    if (node >= N_NODES) return;
    float4 xv = *(const float4*)&x[node * 128 + lane * 4];

    // emit bf16 hi/lo split of this row chunk for the GEMM
    {
        __nv_bfloat16 h0 = __float2bfloat16(xv.x), h1 = __float2bfloat16(xv.y);
        __nv_bfloat16 h2 = __float2bfloat16(xv.z), h3 = __float2bfloat16(xv.w);
        uint32_t hw0 = (uint32_t)__bfloat16_as_ushort(h0) |
                       ((uint32_t)__bfloat16_as_ushort(h1) << 16);
        uint32_t hw1 = (uint32_t)__bfloat16_as_ushort(h2) |
                       ((uint32_t)__bfloat16_as_ushort(h3) << 16);
        float l0 = xv.x - __bfloat162float(h0), l1 = xv.y - __bfloat162float(h1);
        float l2 = xv.z - __bfloat162float(h2), l3 = xv.w - __bfloat162float(h3);
        uint32_t lw0 = (uint32_t)__bfloat16_as_ushort(__float2bfloat16(l0)) |
                       ((uint32_t)__bfloat16_as_ushort(__float2bfloat16(l1)) << 16);
        uint32_t lw1 = (uint32_t)__bfloat16_as_ushort(__float2bfloat16(l2)) |
                       ((uint32_t)__bfloat16_as_ushort(__float2bfloat16(l3)) << 16);
        *(uint2*)&g_xh[node * 128 + lane * 4] = make_uint2(hw0, hw1);
        *(uint2*)&g_xl[node * 128 + lane * 4] = make_uint2(lw0, lw1);
    }

    float r[8];
    #pragma unroll
    for (int j = 0; j < 8; j++) {
        float4 a = *(const float4*)&A2T[j * 128 + lane * 4];
        r[j] = xv.x * a.x + xv.y * a.y + xv.z * a.z + xv.w * a.w;
    }
    #pragma unroll
    for (int o = 16; o; o >>= 1)
        #pragma unroll
        for (int j = 0; j < 8; j++)
            r[j] += __shfl_xor_sync(0xffffffffu, r[j], o);
    if (lane < 8) {
        float v = (lane == 0) ? r[0] : (lane == 1) ? r[1] : (lane == 2) ? r[2] :
                  (lane == 3) ? r[3] : (lane == 4) ? r[4] : (lane == 5) ? r[5] :
                  (lane == 6) ? r[6] : r[7];
        int h = lane & 3;
        if (lane < 4) g_si[node * 4 + h] = v;
        else          g_sj[node * 4 + h] = v;
    }
}

// ---------------- GEMM: mma.sync bf16 3-term split, reg double-buffer ------
#define KP 40

__device__ __forceinline__ void hmma(float* c, const uint32_t* a,
                                     uint32_t b0, uint32_t b1) {
    asm volatile(
        "mma.sync.aligned.m16n8k16.row.col.f32.bf16.bf16.f32 "
        "{%0,%1,%2,%3}, {%4,%5,%6,%7}, {%8,%9}, {%0,%1,%2,%3};"
        : "+f"(c[0]), "+f"(c[1]), "+f"(c[2]), "+f"(c[3])
        : "r"(a[0]), "r"(a[1]), "r"(a[2]), "r"(a[3]), "r"(b0), "r"(b1));
}

__global__ void __launch_bounds__(256)
k_gemm() {
    __shared__ __nv_bfloat16 sAh[128][KP];
    __shared__ __nv_bfloat16 sAl[128][KP];
    __shared__ __nv_bfloat16 sBh[128][KP];
    __shared__ __nv_bfloat16 sBl[128][KP];

    int tid = threadIdx.x;
    int wid = tid >> 5, lane = tid & 31;
    int m0 = blockIdx.x * 128;
    int rb = (wid & 3) * 32;
    int nb = (wid >> 2) * 64;

    // per-thread fill coordinates (constant across stages)
    int row0 = tid >> 2;                 // it = 0
    int row1 = (tid + 256) >> 2;         // it = 1
    int c0   = (tid & 3) * 8;

    float acc[2][8][4];
    #pragma unroll
    for (int mt = 0; mt < 2; mt++)
        #pragma unroll
        for (int nt = 0; nt < 8; nt++)
            #pragma unroll
            for (int q = 0; q < 4; q++) acc[mt][nt][q] = 0.f;

    uint4 pAh[2], pAl[2], pBh[2], pBl[2];
    const uint4 Z = make_uint4(0u, 0u, 0u, 0u);

    // prefetch stage 0
    {
        int rows[2] = {row0, row1};
        #pragma unroll
        for (int it = 0; it < 2; it++) {
            int rr = m0 + rows[it];
            if (rr < N_NODES) {
                pAh[it] = *(const uint4*)&g_xh[rr * 128 + c0];
                pAl[it] = *(const uint4*)&g_xl[rr * 128 + c0];
            } else { pAh[it] = Z; pAl[it] = Z; }
            pBh[it] = *(const uint4*)&g_wth[rows[it] * 128 + c0];
            pBl[it] = *(const uint4*)&g_wtl[rows[it] * 128 + c0];
        }
    }

    for (int st = 0; st < 4; st++) {
        // store prefetched stage into smem
        *(uint4*)&sAh[row0][c0] = pAh[0];
        *(uint4*)&sAh[row1][c0] = pAh[1];
        *(uint4*)&sAl[row0][c0] = pAl[0];
        *(uint4*)&sAl[row1][c0] = pAl[1];
        *(uint4*)&sBh[row0][c0] = pBh[0];
        *(uint4*)&sBh[row1][c0] = pBh[1];
        *(uint4*)&sBl[row0][c0] = pBl[0];
        *(uint4*)&sBl[row1][c0] = pBl[1];
        __syncthreads();

        // prefetch next stage while computing this one
        if (st < 3) {
            int k0 = (st + 1) * 32;
            int rows[2] = {row0, row1};
            #pragma unroll
            for (int it = 0; it < 2; it++) {
                int rr = m0 + rows[it];
                if (rr < N_NODES) {
                    pAh[it] = *(const uint4*)&g_xh[rr * 128 + k0 + c0];
                    pAl[it] = *(const uint4*)&g_xl[rr * 128 + k0 + c0];
                } else { pAh[it] = Z; pAl[it] = Z; }
                pBh[it] = *(const uint4*)&g_wth[rows[it] * 128 + k0 + c0];
                pBl[it] = *(const uint4*)&g_wtl[rows[it] * 128 + k0 + c0];
            }
        }

        #pragma unroll
        for (int ks = 0; ks < 2; ks++) {
            int c = ks * 16 + (lane & 3) * 2;
            uint32_t Ah[2][4], Al[2][4];
            #pragma unroll
            for (int mt = 0; mt < 2; mt++) {
                int r = rb + mt * 16 + (lane >> 2);
                Ah[mt][0] = *(const uint32_t*)&sAh[r][c];
                Ah[mt][1] = *(const uint32_t*)&sAh[r + 8][c];
                Ah[mt][2] = *(const uint32_t*)&sAh[r][c + 8];
                Ah[mt][3] = *(const uint32_t*)&sAh[r + 8][c + 8];
                Al[mt][0] = *(const uint32_t*)&sAl[r][c];
                Al[mt][1] = *(const uint32_t*)&sAl[r + 8][c];
                Al[mt][2] = *(const uint32_t*)&sAl[r][c + 8];
                Al[mt][3] = *(const uint32_t*)&sAl[r + 8][c + 8];
            }
            #pragma unroll
            for (int nt = 0; nt < 8; nt++) {
                int n = nb + nt * 8 + (lane >> 2);
                uint32_t bh0 = *(const uint32_t*)&sBh[n][c];
                uint32_t bh1 = *(const uint32_t*)&sBh[n][c + 8];
                uint32_t bl0 = *(const uint32_t*)&sBl[n][c];
                uint32_t bl1 = *(const uint32_t*)&sBl[n][c + 8];
                #pragma unroll
                for (int mt = 0; mt < 2; mt++) {
                    hmma(acc[mt][nt], Ah[mt], bh0, bh1);
                    hmma(acc[mt][nt], Ah[mt], bl0, bl1);
                    hmma(acc[mt][nt], Al[mt], bh0, bh1);
                }
            }
        }
        __syncthreads();
    }

    #pragma unroll
    for (int mt = 0; mt < 2; mt++) {
        int r0 = m0 + rb + mt * 16 + (lane >> 2);
        #pragma unroll
        for (int nt = 0; nt < 8; nt++) {
            int col = nb + nt * 8 + (lane & 3) * 2;
            if (r0 < N_NODES)
                *(float2*)&g_h[r0 * 128 + col] =
                    make_float2(acc[mt][nt][0], acc[mt][nt][1]);
            if (r0 + 8 < N_NODES)
                *(float2*)&g_h[(r0 + 8) * 128 + col] =
                    make_float2(acc[mt][nt][2], acc[mt][nt][3]);
        }
    }
}

// ---------------- top-k: one thread per (node, head) ------------------------
__global__ void __launch_bounds__(256) k_topk() {
    int t = blockIdx.x * blockDim.x + threadIdx.x;
    if (t >= NPAIRS) return;
    int node = t >> 2;
    int head = t & 3;

    int start = g_off[node];
    int end   = g_off[node + 1];
    float si = g_si[node * HEADS + head];

    unsigned long long top[TOPK];
    #pragma unroll
    for (int r = 0; r < TOPK; r++) top[r] = 0ull;

    for (int i = start; i < end; i++) {
        int c = __ldg(&g_col[i]);
        float s = si + __ldg(&g_sj[c * HEADS + head]);
        s = (s > 0.f) ? s : 0.2f * s;
        unsigned u = __float_as_uint(s);
        u ^= (unsigned)((int)u >> 31) | 0x80000000u;
        unsigned long long key = ((unsigned long long)u << 32) | (unsigned)c;
        if (key > top[TOPK - 1]) {
            top[TOPK - 1] = key;
            #pragma unroll
            for (int r = TOPK - 1; r > 0; r--) {
                unsigned long long a = top[r - 1], b = top[r];
                top[r - 1] = (b > a) ? b : a;
                top[r]     = (b > a) ? a : b;
            }
        }
    }

    int deg = end - start;
    int k = min(deg, TOPK);
    float sc[TOPK];
    #pragma unroll
    for (int r = 0; r < TOPK; r++) {
        unsigned u = (unsigned)(top[r] >> 32);
        u ^= (~((unsigned)((int)u >> 31))) | 0x80000000u;
        sc[r] = __uint_as_float(u);
    }
    float maxe = sc[0];
    float p[TOPK];
    float sum = 0.f;
    #pragma unroll
    for (int r = 0; r < TOPK; r++) {
        float e = (r < k) ? __expf(sc[r] - maxe) : 0.f;
        p[r] = e;
        sum += e;
    }
    float inv = 1.f / sum;
    #pragma unroll
    for (int r = 0; r < TOPK; r++) {
        g_ta[t * TOPK + r] = p[r] * inv;
        g_tc[t * TOPK + r] = (int)(unsigned)(top[r] & 0xffffffffull);
    }
}

// ---------------- aggregate: one warp per (node, head) ----------------------
__global__ void __launch_bounds__(256) k_aggB(float* __restrict__ out) {
    int lane = threadIdx.x & 31;
    int gw = (blockIdx.x * blockDim.x + threadIdx.x) >> 5;
    if (gw >= NPAIRS) return;
    int node = gw >> 2;
    int head = gw & 3;

    float a[TOPK];
    int   c[TOPK];
    #pragma unroll
    for (int r = 0; r < TOPK; r++) {
        a[r] = g_ta[gw * TOPK + r];
        c[r] = g_tc[gw * TOPK + r];
    }
    float acc = 0.f;
    #pragma unroll
    for (int r = 0; r < TOPK; r++)
        acc += a[r] * __ldg(&g_h[c[r] * 128 + head * OUT_CH + lane]);

    out[node * 128 + head * OUT_CH + lane] = (acc > 0.f) ? acc : expm1f(acc);
}

// ---------------- launch (slot 3 = k_gemm for ncu) --------------------------
extern "C" void kernel_launch(void* const* d_in, const int* in_sizes, int n_in,
                              void* d_out, int out_size) {
    const float* x   = (const float*)d_in[0];
    const float* W   = (const float*)d_in[1];
    const float* att = (const float*)d_in[2];
    const int*   ei  = (const int*)d_in[3];
    float* out = (float*)d_out;

    k_prep<<<64, 256>>>(W, att);                                    // 0
    k_hist<<<(N_EDGES / 4 + 255) / 256, 256>>>(ei);                 // 1
    k_scores<<<(N_NODES * 32 + 255) / 256, 256>>>(x);               // 2
    k_gemm<<<(N_NODES + 127) / 128, 256>>>();                       // 3 (profiled)
    k_scan1<<<NB_SCAN, 1024>>>();                                   // 4
    k_scan3<<<NB_SCAN, 1024>>>();                                   // 5
    k_scatter<<<(ET + 255) / 256, 256>>>(ei);                       // 6
    k_topk<<<(NPAIRS + 255) / 256, 256>>>();                        // 7
    k_aggB<<<(NPAIRS * 32 + 255) / 256, 256>>>(out);                // 8
}

// round 8
// speedup vs baseline: 2.0195x; 1.0156x over previous
#include <cuda_runtime.h>
#include <cuda_bf16.h>
#include <math.h>
#include <stdint.h>

#define N_NODES 50000
#define N_EDGES 800000
#define ET (N_EDGES + N_NODES)
#define HEADS 4
#define OUT_CH 32
#define TOPK 8
#define NPAIRS (N_NODES * HEADS)
#define NB_SCAN ((N_NODES + 1023) / 1024)

// ---------------- scratch ----------------
__device__ __align__(16) float g_h[N_NODES * 128];           // 25.6 MB
__device__ __align__(16) __nv_bfloat16 g_xh[N_NODES * 128];  // 12.8 MB
__device__ __align__(16) __nv_bfloat16 g_xl[N_NODES * 128];  // 12.8 MB
__device__ __align__(16) float g_si[NPAIRS];
__device__ __align__(16) float g_sj[NPAIRS];
__device__ int   g_deg[N_NODES + 1];     // .bss zero; reset by scan1 each run
__device__ int   g_off[N_NODES + 1];
__device__ int   g_cur[N_NODES];
__device__ int   g_col[ET];
__device__ int   g_bsum[NB_SCAN + 1];
__device__ __align__(16) float g_ta[NPAIRS * TOPK];
__device__ __align__(16) int   g_tc[NPAIRS * TOPK];
__device__ __align__(16) __nv_bfloat16 g_wth[128 * 128];     // W^T hi [n][k]
__device__ __align__(16) __nv_bfloat16 g_wtl[128 * 128];     // W^T lo [n][k]
__device__ __align__(16) float g_a2[128 * 8];                // W @ att combos

// ---------------- prep ----------------
__global__ void k_prep(const float* __restrict__ W, const float* __restrict__ att) {
    int t = blockIdx.x * blockDim.x + threadIdx.x;
    if (t < 16384) {
        int n = t >> 7, k = t & 127;
        float w = W[k * 128 + n];
        __nv_bfloat16 hi = __float2bfloat16(w);
        float lo = w - __bfloat162float(hi);
        g_wth[n * 128 + k] = hi;
        g_wtl[n * 128 + k] = __float2bfloat16(lo);
    }
    if (t < 1024) {
        int k = t >> 3, j = t & 7;
        int h = j & 3, part = j >> 2;
        float s = 0.f;
        #pragma unroll
        for (int c = 0; c < 32; c++)
            s += W[k * 128 + h * 32 + c] * att[h * 64 + part * 32 + c];
        g_a2[k * 8 + j] = s;
    }
}

// ---------------- CSR build ----------------
__global__ void k_hist(const int* __restrict__ ei) {
    int e = (blockIdx.x * blockDim.x + threadIdx.x) * 4;
    if (e < N_EDGES) {
        int4 v = *(const int4*)&ei[e];
        atomicAdd(&g_deg[v.x], 1);
        atomicAdd(&g_deg[v.y], 1);
        atomicAdd(&g_deg[v.z], 1);
        atomicAdd(&g_deg[v.w], 1);
    }
}

__global__ void k_scan1() {
    __shared__ int wsum[32];
    int tid = threadIdx.x;
    int lane = tid & 31, w = tid >> 5;
    int i = blockIdx.x * 1024 + tid;
    int v = 0;
    if (i < N_NODES) {
        v = g_deg[i] + 1;       // +1 self-loop
        g_deg[i] = 0;           // reset for next graph replay
        g_cur[i] = 0;
    }
    int s = v;
    #pragma unroll
    for (int o = 1; o < 32; o <<= 1) {
        int t = __shfl_up_sync(0xffffffffu, s, o);
        if (lane >= o) s += t;
    }
    if (lane == 31) wsum[w] = s;
    __syncthreads();
    if (w == 0) {
        int t = wsum[lane];
        #pragma unroll
        for (int o = 1; o < 32; o <<= 1) {
            int u = __shfl_up_sync(0xffffffffu, t, o);
            if (lane >= o) t += u;
        }
        wsum[lane] = t;
        if (lane == 31) g_bsum[blockIdx.x] = t;   // block total
    }
    __syncthreads();
    int carry = (w > 0) ? wsum[w - 1] : 0;
    if (i < N_NODES) g_off[i] = s - v + carry;    // exclusive
}

__global__ void k_scan3() {
    __shared__ int carry;
    int tid = threadIdx.x;
    if (tid < 32) {
        int s = 0;
        for (int b = tid; b < blockIdx.x; b += 32) s += g_bsum[b];
        #pragma unroll
        for (int o = 16; o; o >>= 1) s += __shfl_xor_sync(0xffffffffu, s, o);
        if (tid == 0) carry = s;
    }
    __syncthreads();
    int i = blockIdx.x * 1024 + tid;
    if (i < N_NODES) g_off[i] += carry;
    if (i == 0) g_off[N_NODES] = ET;
}

__global__ void k_scatter(const int* __restrict__ ei) {
    int idx = blockIdx.x * blockDim.x + threadIdx.x;
    if (idx >= ET) return;
    int r, c;
    if (idx < N_EDGES) { r = ei[idx]; c = ei[N_EDGES + idx]; }
    else               { r = idx - N_EDGES; c = r; }
    int p = g_off[r] + atomicAdd(&g_cur[r], 1);
    g_col[p] = c;
}

// ---------------- scores + bf16 split of x ----------------------------------
__global__ void k_scores(const float* __restrict__ x) {
    __shared__ float A2T[8 * 128];
    int tid = threadIdx.x;
    for (int i = tid; i < 1024; i += 256) {
        int j = i >> 7, k = i & 127;
        A2T[i] = g_a2[k * 8 + j];
    }
    __syncthreads();
    int lane = tid & 31;
    int node = (blockIdx.x * 256 + tid) >> 5;
    if (node >= N_NODES) return;
    float4 xv = *(const float4*)&x[node * 128 + lane * 4];

    {
        __nv_bfloat16 h0 = __float2bfloat16(xv.x), h1 = __float2bfloat16(xv.y);
        __nv_bfloat16 h2 = __float2bfloat16(xv.z), h3 = __float2bfloat16(xv.w);
        uint32_t hw0 = (uint32_t)__bfloat16_as_ushort(h0) |
                       ((uint32_t)__bfloat16_as_ushort(h1) << 16);
        uint32_t hw1 = (uint32_t)__bfloat16_as_ushort(h2) |
                       ((uint32_t)__bfloat16_as_ushort(h3) << 16);
        float l0 = xv.x - __bfloat162float(h0), l1 = xv.y - __bfloat162float(h1);
        float l2 = xv.z - __bfloat162float(h2), l3 = xv.w - __bfloat162float(h3);
        uint32_t lw0 = (uint32_t)__bfloat16_as_ushort(__float2bfloat16(l0)) |
                       ((uint32_t)__bfloat16_as_ushort(__float2bfloat16(l1)) << 16);
        uint32_t lw1 = (uint32_t)__bfloat16_as_ushort(__float2bfloat16(l2)) |
                       ((uint32_t)__bfloat16_as_ushort(__float2bfloat16(l3)) << 16);
        *(uint2*)&g_xh[node * 128 + lane * 4] = make_uint2(hw0, hw1);
        *(uint2*)&g_xl[node * 128 + lane * 4] = make_uint2(lw0, lw1);
    }

    float r[8];
    #pragma unroll
    for (int j = 0; j < 8; j++) {
        float4 a = *(const float4*)&A2T[j * 128 + lane * 4];
        r[j] = xv.x * a.x + xv.y * a.y + xv.z * a.z + xv.w * a.w;
    }
    #pragma unroll
    for (int o = 16; o; o >>= 1)
        #pragma unroll
        for (int j = 0; j < 8; j++)
            r[j] += __shfl_xor_sync(0xffffffffu, r[j], o);
    if (lane < 8) {
        float v = (lane == 0) ? r[0] : (lane == 1) ? r[1] : (lane == 2) ? r[2] :
                  (lane == 3) ? r[3] : (lane == 4) ? r[4] : (lane == 5) ? r[5] :
                  (lane == 6) ? r[6] : r[7];
        int h = lane & 3;
        if (lane < 4) g_si[node * 4 + h] = v;
        else          g_sj[node * 4 + h] = v;
    }
}

// ---------------- GEMM: mma.sync bf16 3-term split + ldmatrix --------------
#define KP 40

__device__ __forceinline__ void hmma(float* c, const uint32_t* a,
                                     uint32_t b0, uint32_t b1) {
    asm volatile(
        "mma.sync.aligned.m16n8k16.row.col.f32.bf16.bf16.f32 "
        "{%0,%1,%2,%3}, {%4,%5,%6,%7}, {%8,%9}, {%0,%1,%2,%3};"
        : "+f"(c[0]), "+f"(c[1]), "+f"(c[2]), "+f"(c[3])
        : "r"(a[0]), "r"(a[1]), "r"(a[2]), "r"(a[3]), "r"(b0), "r"(b1));
}

#define LDSM4(R, addr) \
    asm volatile("ldmatrix.sync.aligned.m8n8.x4.shared.b16 {%0,%1,%2,%3}, [%4];" \
        : "=r"((R)[0]), "=r"((R)[1]), "=r"((R)[2]), "=r"((R)[3]) : "r"(addr))

__global__ void __launch_bounds__(256, 2)
k_gemm() {
    __shared__ __nv_bfloat16 sAh[128][KP];
    __shared__ __nv_bfloat16 sAl[128][KP];
    __shared__ __nv_bfloat16 sBh[128][KP];
    __shared__ __nv_bfloat16 sBl[128][KP];

    int tid = threadIdx.x;
    int wid = tid >> 5, lane = tid & 31;
    int m0 = blockIdx.x * 128;
    int rb = (wid & 3) * 32;
    int nb = (wid >> 2) * 64;

    float acc[2][8][4];
    #pragma unroll
    for (int mt = 0; mt < 2; mt++)
        #pragma unroll
        for (int nt = 0; nt < 8; nt++)
            #pragma unroll
            for (int q = 0; q < 4; q++) acc[mt][nt][q] = 0.f;

    const uint4 Z = make_uint4(0u, 0u, 0u, 0u);
    int tsub = lane >> 3;       // ldmatrix tile index 0..3
    int trow = lane & 7;        // row within tile

    for (int st = 0; st < 4; st++) {
        int k0 = st * 32;
        #pragma unroll
        for (int it = 0; it < 2; it++) {
            int idx = tid + it * 256;
            int row = idx >> 2;
            int c0 = (idx & 3) * 8;
            int rr = m0 + row;
            uint4 ah = Z, al = Z;
            if (rr < N_NODES) {
                ah = *(const uint4*)&g_xh[rr * 128 + k0 + c0];
                al = *(const uint4*)&g_xl[rr * 128 + k0 + c0];
            }
            *(uint4*)&sAh[row][c0] = ah;
            *(uint4*)&sAl[row][c0] = al;
            *(uint4*)&sBh[row][c0] = *(const uint4*)&g_wth[row * 128 + k0 + c0];
            *(uint4*)&sBl[row][c0] = *(const uint4*)&g_wtl[row * 128 + k0 + c0];
        }
        __syncthreads();

        #pragma unroll
        for (int ks = 0; ks < 2; ks++) {
            int ck = ks * 16;
            uint32_t Ah[2][4], Al[2][4];
            #pragma unroll
            for (int mt = 0; mt < 2; mt++) {
                // tiles: (r,ck) (r+8,ck) (r,ck+8) (r+8,ck+8)
                int r = rb + mt * 16 + ((tsub & 1) << 3) + trow;
                int c = ck + ((tsub >> 1) << 3);
                LDSM4(Ah[mt], (uint32_t)__cvta_generic_to_shared(&sAh[r][c]));
                LDSM4(Al[mt], (uint32_t)__cvta_generic_to_shared(&sAl[r][c]));
            }
            #pragma unroll
            for (int np = 0; np < 4; np++) {
                // tiles: (n0,ck) (n0,ck+8) (n0+8,ck) (n0+8,ck+8)
                int n = nb + np * 16 + ((tsub >> 1) << 3) + trow;
                int c = ck + ((tsub & 1) << 3);
                uint32_t Bh[4], Bl[4];
                LDSM4(Bh, (uint32_t)__cvta_generic_to_shared(&sBh[n][c]));
                LDSM4(Bl, (uint32_t)__cvta_generic_to_shared(&sBl[n][c]));
                #pragma unroll
                for (int mt = 0; mt < 2; mt++) {
                    hmma(acc[mt][2 * np],     Ah[mt], Bh[0], Bh[1]);
                    hmma(acc[mt][2 * np],     Ah[mt], Bl[0], Bl[1]);
                    hmma(acc[mt][2 * np],     Al[mt], Bh[0], Bh[1]);
                    hmma(acc[mt][2 * np + 1], Ah[mt], Bh[2], Bh[3]);
                    hmma(acc[mt][2 * np + 1], Ah[mt], Bl[2], Bl[3]);
                    hmma(acc[mt][2 * np + 1], Al[mt], Bh[2], Bh[3]);
                }
            }
        }
        __syncthreads();
    }

    #pragma unroll
    for (int mt = 0; mt < 2; mt++) {
        int r0 = m0 + rb + mt * 16 + (lane >> 2);
        #pragma unroll
        for (int nt = 0; nt < 8; nt++) {
            int col = nb + nt * 8 + (lane & 3) * 2;
            if (r0 < N_NODES)
                *(float2*)&g_h[r0 * 128 + col] =
                    make_float2(acc[mt][nt][0], acc[mt][nt][1]);
            if (r0 + 8 < N_NODES)
                *(float2*)&g_h[(r0 + 8) * 128 + col] =
                    make_float2(acc[mt][nt][2], acc[mt][nt][3]);
        }
    }
}

// ---------------- top-k: one thread per (node, head) ------------------------
__global__ void __launch_bounds__(256) k_topk() {
    int t = blockIdx.x * blockDim.x + threadIdx.x;
    if (t >= NPAIRS) return;
    int node = t >> 2;
    int head = t & 3;

    int start = g_off[node];
    int end   = g_off[node + 1];
    float si = g_si[node * HEADS + head];

    unsigned long long top[TOPK];
    #pragma unroll
    for (int r = 0; r < TOPK; r++) top[r] = 0ull;

    for (int i = start; i < end; i++) {
        int c = __ldg(&g_col[i]);
        float s = si + __ldg(&g_sj[c * HEADS + head]);
        s = (s > 0.f) ? s : 0.2f * s;
        unsigned u = __float_as_uint(s);
        u ^= (unsigned)((int)u >> 31) | 0x80000000u;
        unsigned long long key = ((unsigned long long)u << 32) | (unsigned)c;
        if (key > top[TOPK - 1]) {
            top[TOPK - 1] = key;
            #pragma unroll
            for (int r = TOPK - 1; r > 0; r--) {
                unsigned long long a = top[r - 1], b = top[r];
                top[r - 1] = (b > a) ? b : a;
                top[r]     = (b > a) ? a : b;
            }
        }
    }

    int deg = end - start;
    int k = min(deg, TOPK);
    float sc[TOPK];
    #pragma unroll
    for (int r = 0; r < TOPK; r++) {
        unsigned u = (unsigned)(top[r] >> 32);
        u ^= (~((unsigned)((int)u >> 31))) | 0x80000000u;
        sc[r] = __uint_as_float(u);
    }
    float maxe = sc[0];
    float p[TOPK];
    float sum = 0.f;
    #pragma unroll
    for (int r = 0; r < TOPK; r++) {
        float e = (r < k) ? __expf(sc[r] - maxe) : 0.f;
        p[r] = e;
        sum += e;
    }
    float inv = 1.f / sum;
    #pragma unroll
    for (int r = 0; r < TOPK; r++) {
        g_ta[t * TOPK + r] = p[r] * inv;
        g_tc[t * TOPK + r] = (int)(unsigned)(top[r] & 0xffffffffull);
    }
}

// ---------------- aggregate: one warp per (node, head) ----------------------
__global__ void __launch_bounds__(256) k_aggB(float* __restrict__ out) {
    int lane = threadIdx.x & 31;
    int gw = (blockIdx.x * blockDim.x + threadIdx.x) >> 5;
    if (gw >= NPAIRS) return;
    int node = gw >> 2;
    int head = gw & 3;

    float a[TOPK];
    int   c[TOPK];
    #pragma unroll
    for (int r = 0; r < TOPK; r++) {
        a[r] = g_ta[gw * TOPK + r];
        c[r] = g_tc[gw * TOPK + r];
    }
    float acc = 0.f;
    #pragma unroll
    for (int r = 0; r < TOPK; r++)
        acc += a[r] * __ldg(&g_h[c[r] * 128 + head * OUT_CH + lane]);

    out[node * 128 + head * OUT_CH + lane] = (acc > 0.f) ? acc : expm1f(acc);
}

// ---------------- launch (slot 3 = k_scatter for ncu) -----------------------
extern "C" void kernel_launch(void* const* d_in, const int* in_sizes, int n_in,
                              void* d_out, int out_size) {
    const float* x   = (const float*)d_in[0];
    const float* W   = (const float*)d_in[1];
    const float* att = (const float*)d_in[2];
    const int*   ei  = (const int*)d_in[3];
    float* out = (float*)d_out;

    k_hist<<<(N_EDGES / 4 + 255) / 256, 256>>>(ei);                 // 0
    k_scan1<<<NB_SCAN, 1024>>>();                                   // 1
    k_scan3<<<NB_SCAN, 1024>>>();                                   // 2
    k_scatter<<<(ET + 255) / 256, 256>>>(ei);                       // 3 (profiled)
    k_prep<<<64, 256>>>(W, att);                                    // 4
    k_scores<<<(N_NODES * 32 + 255) / 256, 256>>>(x);               // 5
    k_gemm<<<(N_NODES + 127) / 128, 256>>>();                       // 6
    k_topk<<<(NPAIRS + 255) / 256, 256>>>();                        // 7
    k_aggB<<<(NPAIRS * 32 + 255) / 256, 256>>>(out);                // 8
}

// round 9
// speedup vs baseline: 2.0758x; 1.0279x over previous
#include <cuda_runtime.h>
#include <cuda_bf16.h>
#include <math.h>
#include <stdint.h>

#define N_NODES 50000
#define N_EDGES 800000
#define ET (N_EDGES + N_NODES)
#define HEADS 4
#define OUT_CH 32
#define TOPK 8
#define NPAIRS (N_NODES * HEADS)
#define NB_SCAN ((N_NODES + 1023) / 1024)

// ---------------- scratch ----------------
__device__ __align__(16) float g_h[N_NODES * 128];           // 25.6 MB
__device__ __align__(16) float g_si[NPAIRS];
__device__ __align__(16) uint32_t g_usk[NPAIRS];             // monotone(sj) keys
__device__ int   g_deg[N_NODES + 1];     // .bss zero; reset by scan1 each run
__device__ int   g_off[N_NODES + 1];
__device__ int   g_cur[N_NODES];
__device__ int   g_col[ET];
__device__ int   g_bsum[NB_SCAN + 1];
__device__ __align__(16) __nv_bfloat16 g_wth[128 * 128];     // W^T hi [n][k]
__device__ __align__(16) __nv_bfloat16 g_wtl[128 * 128];     // W^T lo [n][k]
__device__ __align__(16) float g_a2[128 * 8];                // W @ att combos

// ---------------- prep ----------------
__global__ void k_prep(const float* __restrict__ W, const float* __restrict__ att) {
    int t = blockIdx.x * blockDim.x + threadIdx.x;
    if (t < 16384) {
        int n = t >> 7, k = t & 127;
        float w = W[k * 128 + n];
        __nv_bfloat16 hi = __float2bfloat16(w);
        float lo = w - __bfloat162float(hi);
        g_wth[n * 128 + k] = hi;
        g_wtl[n * 128 + k] = __float2bfloat16(lo);
    }
    if (t < 1024) {
        int k = t >> 3, j = t & 7;
        int h = j & 3, part = j >> 2;
        float s = 0.f;
        #pragma unroll
        for (int c = 0; c < 32; c++)
            s += W[k * 128 + h * 32 + c] * att[h * 64 + part * 32 + c];
        g_a2[k * 8 + j] = s;
    }
}

// ---------------- CSR build ----------------
__global__ void k_hist(const int* __restrict__ ei) {
    int e = (blockIdx.x * blockDim.x + threadIdx.x) * 4;
    if (e < N_EDGES) {
        int4 v = *(const int4*)&ei[e];
        atomicAdd(&g_deg[v.x], 1);
        atomicAdd(&g_deg[v.y], 1);
        atomicAdd(&g_deg[v.z], 1);
        atomicAdd(&g_deg[v.w], 1);
    }
}

__global__ void k_scan1() {
    __shared__ int wsum[32];
    int tid = threadIdx.x;
    int lane = tid & 31, w = tid >> 5;
    int i = blockIdx.x * 1024 + tid;
    int v = 0;
    if (i < N_NODES) {
        v = g_deg[i] + 1;       // +1 self-loop
        g_deg[i] = 0;           // reset for next graph replay
        g_cur[i] = 0;
    }
    int s = v;
    #pragma unroll
    for (int o = 1; o < 32; o <<= 1) {
        int t = __shfl_up_sync(0xffffffffu, s, o);
        if (lane >= o) s += t;
    }
    if (lane == 31) wsum[w] = s;
    __syncthreads();
    if (w == 0) {
        int t = wsum[lane];
        #pragma unroll
        for (int o = 1; o < 32; o <<= 1) {
            int u = __shfl_up_sync(0xffffffffu, t, o);
            if (lane >= o) t += u;
        }
        wsum[lane] = t;
        if (lane == 31) g_bsum[blockIdx.x] = t;
    }
    __syncthreads();
    int carry = (w > 0) ? wsum[w - 1] : 0;
    if (i < N_NODES) g_off[i] = s - v + carry;
}

__global__ void k_scan3() {
    __shared__ int carry;
    int tid = threadIdx.x;
    if (tid < 32) {
        int s = 0;
        for (int b = tid; b < blockIdx.x; b += 32) s += g_bsum[b];
        #pragma unroll
        for (int o = 16; o; o >>= 1) s += __shfl_xor_sync(0xffffffffu, s, o);
        if (tid == 0) carry = s;
    }
    __syncthreads();
    int i = blockIdx.x * 1024 + tid;
    if (i < N_NODES) g_off[i] += carry;
    if (i == 0) g_off[N_NODES] = ET;
}

__global__ void k_scatter(const int* __restrict__ ei) {
    int idx = blockIdx.x * blockDim.x + threadIdx.x;
    if (idx >= ET) return;
    int r, c;
    if (idx < N_EDGES) { r = ei[idx]; c = ei[N_EDGES + idx]; }
    else               { r = idx - N_EDGES; c = r; }
    int p = g_off[r] + atomicAdd(&g_cur[r], 1);
    g_col[p] = c;
}

// ---------------- scores: s_i float + monotone-u32 key of s_j --------------
__global__ void k_scores(const float* __restrict__ x) {
    __shared__ float A2T[8 * 128];
    int tid = threadIdx.x;
    for (int i = tid; i < 1024; i += 256) {
        int j = i >> 7, k = i & 127;
        A2T[i] = g_a2[k * 8 + j];
    }
    __syncthreads();
    int lane = tid & 31;
    int node = (blockIdx.x * 256 + tid) >> 5;
    if (node >= N_NODES) return;
    float4 xv = *(const float4*)&x[node * 128 + lane * 4];
    float r[8];
    #pragma unroll
    for (int j = 0; j < 8; j++) {
        float4 a = *(const float4*)&A2T[j * 128 + lane * 4];
        r[j] = xv.x * a.x + xv.y * a.y + xv.z * a.z + xv.w * a.w;
    }
    #pragma unroll
    for (int o = 16; o; o >>= 1)
        #pragma unroll
        for (int j = 0; j < 8; j++)
            r[j] += __shfl_xor_sync(0xffffffffu, r[j], o);
    if (lane < 8) {
        float v = (lane == 0) ? r[0] : (lane == 1) ? r[1] : (lane == 2) ? r[2] :
                  (lane == 3) ? r[3] : (lane == 4) ? r[4] : (lane == 5) ? r[5] :
                  (lane == 6) ? r[6] : r[7];
        int h = lane & 3;
        if (lane < 4) {
            g_si[node * 4 + h] = v;
        } else {
            unsigned u = __float_as_uint(v);
            u ^= (unsigned)((int)u >> 31) | 0x80000000u;   // monotone map
            g_usk[node * 4 + h] = u;
        }
    }
}

// ---------------- GEMM: mma.sync bf16 3-term split + ldmatrix --------------
#define KP 40

__device__ __forceinline__ void hmma(float* c, const uint32_t* a,
                                     uint32_t b0, uint32_t b1) {
    asm volatile(
        "mma.sync.aligned.m16n8k16.row.col.f32.bf16.bf16.f32 "
        "{%0,%1,%2,%3}, {%4,%5,%6,%7}, {%8,%9}, {%0,%1,%2,%3};"
        : "+f"(c[0]), "+f"(c[1]), "+f"(c[2]), "+f"(c[3])
        : "r"(a[0]), "r"(a[1]), "r"(a[2]), "r"(a[3]), "r"(b0), "r"(b1));
}

#define LDSM4(R, addr) \
    asm volatile("ldmatrix.sync.aligned.m8n8.x4.shared.b16 {%0,%1,%2,%3}, [%4];" \
        : "=r"((R)[0]), "=r"((R)[1]), "=r"((R)[2]), "=r"((R)[3]) : "r"(addr))

__global__ void __launch_bounds__(256, 2)
k_gemm(const float* __restrict__ x) {
    __shared__ __nv_bfloat16 sAh[128][KP];
    __shared__ __nv_bfloat16 sAl[128][KP];
    __shared__ __nv_bfloat16 sBh[128][KP];
    __shared__ __nv_bfloat16 sBl[128][KP];

    int tid = threadIdx.x;
    int wid = tid >> 5, lane = tid & 31;
    int m0 = blockIdx.x * 128;
    int rb = (wid & 3) * 32;
    int nb = (wid >> 2) * 64;

    float acc[2][8][4];
    #pragma unroll
    for (int mt = 0; mt < 2; mt++)
        #pragma unroll
        for (int nt = 0; nt < 8; nt++)
            #pragma unroll
            for (int q = 0; q < 4; q++) acc[mt][nt][q] = 0.f;

    int tsub = lane >> 3;
    int trow = lane & 7;

    for (int st = 0; st < 4; st++) {
        int k0 = st * 32;
        #pragma unroll
        for (int it = 0; it < 2; it++) {
            int idx = tid + it * 256;
            int row = idx >> 2;
            int c0 = (idx & 3) * 8;
            int rr = m0 + row;
            float4 v0 = make_float4(0.f, 0.f, 0.f, 0.f), v1 = v0;
            if (rr < N_NODES) {
                v0 = *(const float4*)&x[rr * 128 + k0 + c0];
                v1 = *(const float4*)&x[rr * 128 + k0 + c0 + 4];
            }
            float vs[8] = {v0.x, v0.y, v0.z, v0.w, v1.x, v1.y, v1.z, v1.w};
            uint32_t hw[4], lw[4];
            #pragma unroll
            for (int q = 0; q < 4; q++) {
                __nv_bfloat16 h0 = __float2bfloat16(vs[2 * q]);
                __nv_bfloat16 h1 = __float2bfloat16(vs[2 * q + 1]);
                float l0 = vs[2 * q] - __bfloat162float(h0);
                float l1 = vs[2 * q + 1] - __bfloat162float(h1);
                hw[q] = (uint32_t)__bfloat16_as_ushort(h0) |
                        ((uint32_t)__bfloat16_as_ushort(h1) << 16);
                lw[q] = (uint32_t)__bfloat16_as_ushort(__float2bfloat16(l0)) |
                        ((uint32_t)__bfloat16_as_ushort(__float2bfloat16(l1)) << 16);
            }
            *(uint4*)&sAh[row][c0] = make_uint4(hw[0], hw[1], hw[2], hw[3]);
            *(uint4*)&sAl[row][c0] = make_uint4(lw[0], lw[1], lw[2], lw[3]);
            *(uint4*)&sBh[row][c0] = *(const uint4*)&g_wth[row * 128 + k0 + c0];
            *(uint4*)&sBl[row][c0] = *(const uint4*)&g_wtl[row * 128 + k0 + c0];
        }
        __syncthreads();

        #pragma unroll
        for (int ks = 0; ks < 2; ks++) {
            int ck = ks * 16;
            uint32_t Ah[2][4], Al[2][4];
            #pragma unroll
            for (int mt = 0; mt < 2; mt++) {
                int r = rb + mt * 16 + ((tsub & 1) << 3) + trow;
                int c = ck + ((tsub >> 1) << 3);
                LDSM4(Ah[mt], (uint32_t)__cvta_generic_to_shared(&sAh[r][c]));
                LDSM4(Al[mt], (uint32_t)__cvta_generic_to_shared(&sAl[r][c]));
            }
            #pragma unroll
            for (int np = 0; np < 4; np++) {
                int n = nb + np * 16 + ((tsub >> 1) << 3) + trow;
                int c = ck + ((tsub & 1) << 3);
                uint32_t Bh[4], Bl[4];
                LDSM4(Bh, (uint32_t)__cvta_generic_to_shared(&sBh[n][c]));
                LDSM4(Bl, (uint32_t)__cvta_generic_to_shared(&sBl[n][c]));
                #pragma unroll
                for (int mt = 0; mt < 2; mt++) {
                    hmma(acc[mt][2 * np],     Ah[mt], Bh[0], Bh[1]);
                    hmma(acc[mt][2 * np],     Ah[mt], Bl[0], Bl[1]);
                    hmma(acc[mt][2 * np],     Al[mt], Bh[0], Bh[1]);
                    hmma(acc[mt][2 * np + 1], Ah[mt], Bh[2], Bh[3]);
                    hmma(acc[mt][2 * np + 1], Ah[mt], Bl[2], Bl[3]);
                    hmma(acc[mt][2 * np + 1], Al[mt], Bh[2], Bh[3]);
                }
            }
        }
        __syncthreads();
    }

    #pragma unroll
    for (int mt = 0; mt < 2; mt++) {
        int r0 = m0 + rb + mt * 16 + (lane >> 2);
        #pragma unroll
        for (int nt = 0; nt < 8; nt++) {
            int col = nb + nt * 8 + (lane & 3) * 2;
            if (r0 < N_NODES)
                *(float2*)&g_h[r0 * 128 + col] =
                    make_float2(acc[mt][nt][0], acc[mt][nt][1]);
            if (r0 + 8 < N_NODES)
                *(float2*)&g_h[(r0 + 8) * 128 + col] =
                    make_float2(acc[mt][nt][2], acc[mt][nt][3]);
        }
    }
}

// ---------------- fused top-k + softmax + aggregate + ELU -------------------
// Phase 1: thread per (node,head) — select top-8 by precomputed sj-key.
// Phase 2: warp per (node,head) — gather h rows, weighted sum, ELU.
__global__ void __launch_bounds__(256) k_topkagg(float* __restrict__ out) {
    __shared__ float salpha[256][TOPK];
    __shared__ int   scol[256][TOPK];

    int tid = threadIdx.x;
    int gw0 = blockIdx.x * 256;

    // ---- phase 1
    {
        int gw = gw0 + tid;
        if (gw < NPAIRS) {
            int node = gw >> 2;
            int head = gw & 3;
            int start = g_off[node];
            int end   = g_off[node + 1];

            unsigned long long top[TOPK];
            #pragma unroll
            for (int r = 0; r < TOPK; r++) top[r] = 0ull;

            for (int i = start; i < end; i++) {
                int c = __ldg(&g_col[i]);
                uint32_t u = __ldg(&g_usk[c * 4 + head]);
                unsigned long long key = ((unsigned long long)u << 32) | (unsigned)c;
                if (key > top[TOPK - 1]) {
                    top[TOPK - 1] = key;
                    #pragma unroll
                    for (int r = TOPK - 1; r > 0; r--) {
                        unsigned long long a = top[r - 1], b = top[r];
                        top[r - 1] = (b > a) ? b : a;
                        top[r]     = (b > a) ? a : b;
                    }
                }
            }

            int deg = end - start;
            int k = min(deg, TOPK);
            float si = g_si[gw];
            float sc[TOPK];
            #pragma unroll
            for (int r = 0; r < TOPK; r++) {
                unsigned u = (unsigned)(top[r] >> 32);
                u ^= (~((unsigned)((int)u >> 31))) | 0x80000000u;  // inverse map
                float s = si + __uint_as_float(u);
                sc[r] = (s > 0.f) ? s : 0.2f * s;                  // leaky
            }
            float maxe = sc[0];
            float p[TOPK];
            float sum = 0.f;
            #pragma unroll
            for (int r = 0; r < TOPK; r++) {
                float e = (r < k) ? __expf(sc[r] - maxe) : 0.f;
                p[r] = e;
                sum += e;
            }
            float inv = 1.f / sum;
            #pragma unroll
            for (int r = 0; r < TOPK; r++) {
                salpha[tid][r] = p[r] * inv;
                scol[tid][r]   = (int)(unsigned)(top[r] & 0xffffffffull);
            }
        } else {
            #pragma unroll
            for (int r = 0; r < TOPK; r++) { salpha[tid][r] = 0.f; scol[tid][r] = 0; }
        }
    }
    __syncthreads();

    // ---- phase 2: warp per pair, 32 pairs per warp
    int wid = tid >> 5, lane = tid & 31;
    for (int p = 0; p < 32; p++) {
        int lp = wid * 32 + p;
        int gw = gw0 + lp;
        if (gw >= NPAIRS) break;
        int node = gw >> 2;
        int head = gw & 3;
        float acc = 0.f;
        #pragma unroll
        for (int r = 0; r < TOPK; r++) {
            float a = salpha[lp][r];          // broadcast
            int   c = scol[lp][r];
            acc += a * __ldg(&g_h[c * 128 + head * OUT_CH + lane]);
        }
        out[node * 128 + head * OUT_CH + lane] = (acc > 0.f) ? acc : expm1f(acc);
    }
}

// ---------------- launch (slot 3 = k_gemm for ncu) --------------------------
extern "C" void kernel_launch(void* const* d_in, const int* in_sizes, int n_in,
                              void* d_out, int out_size) {
    const float* x   = (const float*)d_in[0];
    const float* W   = (const float*)d_in[1];
    const float* att = (const float*)d_in[2];
    const int*   ei  = (const int*)d_in[3];
    float* out = (float*)d_out;

    k_prep<<<64, 256>>>(W, att);                                    // 0
    k_scores<<<(N_NODES * 32 + 255) / 256, 256>>>(x);               // 1
    k_hist<<<(N_EDGES / 4 + 255) / 256, 256>>>(ei);                 // 2
    k_gemm<<<(N_NODES + 127) / 128, 256>>>(x);                      // 3 (profiled)
    k_scan1<<<NB_SCAN, 1024>>>();                                   // 4
    k_scan3<<<NB_SCAN, 1024>>>();                                   // 5
    k_scatter<<<(ET + 255) / 256, 256>>>(ei);                       // 6
    k_topkagg<<<(NPAIRS + 255) / 256, 256>>>(out);                  // 7
}

// round 10
// speedup vs baseline: 2.1431x; 1.0324x over previous
#include <cuda_runtime.h>
#include <cuda_bf16.h>
#include <math.h>
#include <stdint.h>

#define N_NODES 50000
#define N_EDGES 800000
#define ET (N_EDGES + N_NODES)
#define HEADS 4
#define OUT_CH 32
#define TOPK 8
#define NPAIRS (N_NODES * HEADS)
#define NB_SCAN ((N_NODES + 1023) / 1024)
typedef unsigned long long ull;

// ---------------- scratch ----------------
__device__ __align__(16) float g_h[N_NODES * 128];           // 25.6 MB
__device__ __align__(16) float g_si[NPAIRS];
__device__ __align__(16) uint32_t g_usk[NPAIRS];             // monotone(sj) keys
__device__ int   g_deg[N_NODES + 1];     // .bss zero; reset by scan1 each run
__device__ int   g_off[N_NODES + 1];
__device__ int   g_cur[N_NODES];
__device__ int   g_col[ET];
__device__ int   g_bsum[NB_SCAN + 1];
__device__ __align__(16) __nv_bfloat16 g_wth[128 * 128];     // W^T hi [n][k]
__device__ __align__(16) __nv_bfloat16 g_wtl[128 * 128];     // W^T lo [n][k]
__device__ __align__(16) float g_a2[128 * 8];                // W @ att combos

// ---------------- prep ----------------
__global__ void k_prep(const float* __restrict__ W, const float* __restrict__ att) {
    int t = blockIdx.x * blockDim.x + threadIdx.x;
    if (t < 16384) {
        int n = t >> 7, k = t & 127;
        float w = W[k * 128 + n];
        __nv_bfloat16 hi = __float2bfloat16(w);
        float lo = w - __bfloat162float(hi);
        g_wth[n * 128 + k] = hi;
        g_wtl[n * 128 + k] = __float2bfloat16(lo);
    }
    if (t < 1024) {
        int k = t >> 3, j = t & 7;
        int h = j & 3, part = j >> 2;
        float s = 0.f;
        #pragma unroll
        for (int c = 0; c < 32; c++)
            s += W[k * 128 + h * 32 + c] * att[h * 64 + part * 32 + c];
        g_a2[k * 8 + j] = s;
    }
}

// ---------------- CSR build ----------------
__global__ void k_hist(const int* __restrict__ ei) {
    int e = (blockIdx.x * blockDim.x + threadIdx.x) * 4;
    if (e < N_EDGES) {
        int4 v = *(const int4*)&ei[e];
        atomicAdd(&g_deg[v.x], 1);
        atomicAdd(&g_deg[v.y], 1);
        atomicAdd(&g_deg[v.z], 1);
        atomicAdd(&g_deg[v.w], 1);
    }
}

__global__ void k_scan1() {
    __shared__ int wsum[32];
    int tid = threadIdx.x;
    int lane = tid & 31, w = tid >> 5;
    int i = blockIdx.x * 1024 + tid;
    int v = 0;
    if (i < N_NODES) {
        v = g_deg[i] + 1;       // +1 self-loop
        g_deg[i] = 0;           // reset for next graph replay
        g_cur[i] = 0;
    }
    int s = v;
    #pragma unroll
    for (int o = 1; o < 32; o <<= 1) {
        int t = __shfl_up_sync(0xffffffffu, s, o);
        if (lane >= o) s += t;
    }
    if (lane == 31) wsum[w] = s;
    __syncthreads();
    if (w == 0) {
        int t = wsum[lane];
        #pragma unroll
        for (int o = 1; o < 32; o <<= 1) {
            int u = __shfl_up_sync(0xffffffffu, t, o);
            if (lane >= o) t += u;
        }
        wsum[lane] = t;
        if (lane == 31) g_bsum[blockIdx.x] = t;
    }
    __syncthreads();
    int carry = (w > 0) ? wsum[w - 1] : 0;
    if (i < N_NODES) g_off[i] = s - v + carry;
}

__global__ void k_scan3() {
    __shared__ int carry;
    int tid = threadIdx.x;
    if (tid < 32) {
        int s = 0;
        for (int b = tid; b < blockIdx.x; b += 32) s += g_bsum[b];
        #pragma unroll
        for (int o = 16; o; o >>= 1) s += __shfl_xor_sync(0xffffffffu, s, o);
        if (tid == 0) carry = s;
    }
    __syncthreads();
    int i = blockIdx.x * 1024 + tid;
    if (i < N_NODES) g_off[i] += carry;
    if (i == 0) g_off[N_NODES] = ET;
}

__global__ void k_scatter(const int* __restrict__ ei) {
    int idx = blockIdx.x * blockDim.x + threadIdx.x;
    if (idx >= ET) return;
    int r, c;
    if (idx < N_EDGES) { r = ei[idx]; c = ei[N_EDGES + idx]; }
    else               { r = idx - N_EDGES; c = r; }
    int p = g_off[r] + atomicAdd(&g_cur[r], 1);
    g_col[p] = c;
}

// ---------------- scores: s_i float + monotone-u32 key of s_j --------------
__global__ void k_scores(const float* __restrict__ x) {
    __shared__ float A2T[8 * 128];
    int tid = threadIdx.x;
    for (int i = tid; i < 1024; i += 256) {
        int j = i >> 7, k = i & 127;
        A2T[i] = g_a2[k * 8 + j];
    }
    __syncthreads();
    int lane = tid & 31;
    int node = (blockIdx.x * 256 + tid) >> 5;
    if (node >= N_NODES) return;
    float4 xv = *(const float4*)&x[node * 128 + lane * 4];
    float r[8];
    #pragma unroll
    for (int j = 0; j < 8; j++) {
        float4 a = *(const float4*)&A2T[j * 128 + lane * 4];
        r[j] = xv.x * a.x + xv.y * a.y + xv.z * a.z + xv.w * a.w;
    }
    #pragma unroll
    for (int o = 16; o; o >>= 1)
        #pragma unroll
        for (int j = 0; j < 8; j++)
            r[j] += __shfl_xor_sync(0xffffffffu, r[j], o);
    if (lane < 8) {
        float v = (lane == 0) ? r[0] : (lane == 1) ? r[1] : (lane == 2) ? r[2] :
                  (lane == 3) ? r[3] : (lane == 4) ? r[4] : (lane == 5) ? r[5] :
                  (lane == 6) ? r[6] : r[7];
        int h = lane & 3;
        if (lane < 4) {
            g_si[node * 4 + h] = v;
        } else {
            unsigned u = __float_as_uint(v);
            u ^= (unsigned)((int)u >> 31) | 0x80000000u;   // monotone map
            g_usk[node * 4 + h] = u;
        }
    }
}

// ---------------- GEMM: mma.sync bf16 3-term split + ldmatrix --------------
#define KP 40

__device__ __forceinline__ void hmma(float* c, const uint32_t* a,
                                     uint32_t b0, uint32_t b1) {
    asm volatile(
        "mma.sync.aligned.m16n8k16.row.col.f32.bf16.bf16.f32 "
        "{%0,%1,%2,%3}, {%4,%5,%6,%7}, {%8,%9}, {%0,%1,%2,%3};"
        : "+f"(c[0]), "+f"(c[1]), "+f"(c[2]), "+f"(c[3])
        : "r"(a[0]), "r"(a[1]), "r"(a[2]), "r"(a[3]), "r"(b0), "r"(b1));
}

#define LDSM4(R, addr) \
    asm volatile("ldmatrix.sync.aligned.m8n8.x4.shared.b16 {%0,%1,%2,%3}, [%4];" \
        : "=r"((R)[0]), "=r"((R)[1]), "=r"((R)[2]), "=r"((R)[3]) : "r"(addr))

__global__ void __launch_bounds__(256, 2)
k_gemm(const float* __restrict__ x) {
    __shared__ __nv_bfloat16 sAh[128][KP];
    __shared__ __nv_bfloat16 sAl[128][KP];
    __shared__ __nv_bfloat16 sBh[128][KP];
    __shared__ __nv_bfloat16 sBl[128][KP];

    int tid = threadIdx.x;
    int wid = tid >> 5, lane = tid & 31;
    int m0 = blockIdx.x * 128;
    int rb = (wid & 3) * 32;
    int nb = (wid >> 2) * 64;

    float acc[2][8][4];
    #pragma unroll
    for (int mt = 0; mt < 2; mt++)
        #pragma unroll
        for (int nt = 0; nt < 8; nt++)
            #pragma unroll
            for (int q = 0; q < 4; q++) acc[mt][nt][q] = 0.f;

    int tsub = lane >> 3;
    int trow = lane & 7;

    for (int st = 0; st < 4; st++) {
        int k0 = st * 32;
        #pragma unroll
        for (int it = 0; it < 2; it++) {
            int idx = tid + it * 256;
            int row = idx >> 2;
            int c0 = (idx & 3) * 8;
            int rr = m0 + row;
            float4 v0 = make_float4(0.f, 0.f, 0.f, 0.f), v1 = v0;
            if (rr < N_NODES) {
                v0 = *(const float4*)&x[rr * 128 + k0 + c0];
                v1 = *(const float4*)&x[rr * 128 + k0 + c0 + 4];
            }
            float vs[8] = {v0.x, v0.y, v0.z, v0.w, v1.x, v1.y, v1.z, v1.w};
            uint32_t hw[4], lw[4];
            #pragma unroll
            for (int q = 0; q < 4; q++) {
                __nv_bfloat16 h0 = __float2bfloat16(vs[2 * q]);
                __nv_bfloat16 h1 = __float2bfloat16(vs[2 * q + 1]);
                float l0 = vs[2 * q] - __bfloat162float(h0);
                float l1 = vs[2 * q + 1] - __bfloat162float(h1);
                hw[q] = (uint32_t)__bfloat16_as_ushort(h0) |
                        ((uint32_t)__bfloat16_as_ushort(h1) << 16);
                lw[q] = (uint32_t)__bfloat16_as_ushort(__float2bfloat16(l0)) |
                        ((uint32_t)__bfloat16_as_ushort(__float2bfloat16(l1)) << 16);
            }
            *(uint4*)&sAh[row][c0] = make_uint4(hw[0], hw[1], hw[2], hw[3]);
            *(uint4*)&sAl[row][c0] = make_uint4(lw[0], lw[1], lw[2], lw[3]);
            *(uint4*)&sBh[row][c0] = *(const uint4*)&g_wth[row * 128 + k0 + c0];
            *(uint4*)&sBl[row][c0] = *(const uint4*)&g_wtl[row * 128 + k0 + c0];
        }
        __syncthreads();

        #pragma unroll
        for (int ks = 0; ks < 2; ks++) {
            int ck = ks * 16;
            uint32_t Ah[2][4], Al[2][4];
            #pragma unroll
            for (int mt = 0; mt < 2; mt++) {
                int r = rb + mt * 16 + ((tsub & 1) << 3) + trow;
                int c = ck + ((tsub >> 1) << 3);
                LDSM4(Ah[mt], (uint32_t)__cvta_generic_to_shared(&sAh[r][c]));
                LDSM4(Al[mt], (uint32_t)__cvta_generic_to_shared(&sAl[r][c]));
            }
            #pragma unroll
            for (int np = 0; np < 4; np++) {
                int n = nb + np * 16 + ((tsub >> 1) << 3) + trow;
                int c = ck + ((tsub & 1) << 3);
                uint32_t Bh[4], Bl[4];
                LDSM4(Bh, (uint32_t)__cvta_generic_to_shared(&sBh[n][c]));
                LDSM4(Bl, (uint32_t)__cvta_generic_to_shared(&sBl[n][c]));
                #pragma unroll
                for (int mt = 0; mt < 2; mt++) {
                    hmma(acc[mt][2 * np],     Ah[mt], Bh[0], Bh[1]);
                    hmma(acc[mt][2 * np],     Ah[mt], Bl[0], Bl[1]);
                    hmma(acc[mt][2 * np],     Al[mt], Bh[0], Bh[1]);
                    hmma(acc[mt][2 * np + 1], Ah[mt], Bh[2], Bh[3]);
                    hmma(acc[mt][2 * np + 1], Ah[mt], Bl[2], Bl[3]);
                    hmma(acc[mt][2 * np + 1], Al[mt], Bh[2], Bh[3]);
                }
            }
        }
        __syncthreads();
    }

    #pragma unroll
    for (int mt = 0; mt < 2; mt++) {
        int r0 = m0 + rb + mt * 16 + (lane >> 2);
        #pragma unroll
        for (int nt = 0; nt < 8; nt++) {
            int col = nb + nt * 8 + (lane & 3) * 2;
            if (r0 < N_NODES)
                *(float2*)&g_h[r0 * 128 + col] =
                    make_float2(acc[mt][nt][0], acc[mt][nt][1]);
            if (r0 + 8 < N_NODES)
                *(float2*)&g_h[(r0 + 8) * 128 + col] =
                    make_float2(acc[mt][nt][2], acc[mt][nt][3]);
        }
    }
}

// ---------------- fused top-k + softmax + aggregate + ELU -------------------
#define CSWAP(a, b) { ull _x = key[a], _y = key[b]; \
                      key[a] = (_x > _y) ? _x : _y; key[b] = (_x > _y) ? _y : _x; }
#define BUBBLE() { CSWAP(6,7) CSWAP(5,6) CSWAP(4,5) CSWAP(3,4) \
                   CSWAP(2,3) CSWAP(1,2) CSWAP(0,1) }

__global__ void __launch_bounds__(256) k_topkagg(float* __restrict__ out) {
    __shared__ float salpha[256][TOPK];
    __shared__ int   scol[256][TOPK];

    int tid = threadIdx.x;
    int gw0 = blockIdx.x * 256;

    // ---- phase 1: thread per (node,head)
    {
        int gw = gw0 + tid;
        if (gw < NPAIRS) {
            int node = gw >> 2;
            int head = gw & 3;
            int start = g_off[node];
            int end   = g_off[node + 1];
            int deg = end - start;

            // batch-load first 8 (MLP=8), pad with 0
            ull key[8];
            #pragma unroll
            for (int r = 0; r < 8; r++) {
                ull kv = 0ull;
                if (r < deg) {
                    int c = g_col[start + r];
                    uint32_t u = g_usk[c * 4 + head];
                    kv = ((ull)u << 32) | (unsigned)c;
                }
                key[r] = kv;
            }
            // Batcher odd-even sort-8 (19 CEs), descending
            CSWAP(0,1) CSWAP(2,3) CSWAP(4,5) CSWAP(6,7)
            CSWAP(0,2) CSWAP(1,3) CSWAP(4,6) CSWAP(5,7)
            CSWAP(1,2) CSWAP(5,6)
            CSWAP(0,4) CSWAP(1,5) CSWAP(2,6) CSWAP(3,7)
            CSWAP(2,4) CSWAP(3,5)
            CSWAP(1,2) CSWAP(3,4) CSWAP(5,6)

            // filtered insertion for the rest, unrolled x2
            int i = start + 8;
            for (; i + 1 < end; i += 2) {
                int c0 = g_col[i], c1 = g_col[i + 1];
                uint32_t u0 = g_usk[c0 * 4 + head];
                uint32_t u1 = g_usk[c1 * 4 + head];
                ull k0 = ((ull)u0 << 32) | (unsigned)c0;
                ull k1 = ((ull)u1 << 32) | (unsigned)c1;
                if (k0 > key[7]) { key[7] = k0; BUBBLE() }
                if (k1 > key[7]) { key[7] = k1; BUBBLE() }
            }
            if (i < end) {
                int c = g_col[i];
                uint32_t u = g_usk[c * 4 + head];
                ull kv = ((ull)u << 32) | (unsigned)c;
                if (kv > key[7]) { key[7] = kv; BUBBLE() }
            }

            int k = min(deg, TOPK);
            float si = g_si[gw];
            float sc[TOPK];
            #pragma unroll
            for (int r = 0; r < TOPK; r++) {
                unsigned u = (unsigned)(key[r] >> 32);
                u ^= (~((unsigned)((int)u >> 31))) | 0x80000000u;  // inverse map
                float s = si + __uint_as_float(u);
                sc[r] = (s > 0.f) ? s : 0.2f * s;                  // leaky
            }
            float maxe = sc[0];
            float p[TOPK];
            float sum = 0.f;
            #pragma unroll
            for (int r = 0; r < TOPK; r++) {
                float e = (r < k) ? __expf(sc[r] - maxe) : 0.f;
                p[r] = e;
                sum += e;
            }
            float inv = 1.f / sum;
            #pragma unroll
            for (int r = 0; r < TOPK; r++) {
                salpha[tid][r] = p[r] * inv;
                scol[tid][r]   = (int)(unsigned)(key[r] & 0xffffffffull);
            }
        } else {
            #pragma unroll
            for (int r = 0; r < TOPK; r++) { salpha[tid][r] = 0.f; scol[tid][r] = 0; }
        }
    }
    __syncthreads();

    // ---- phase 2: warp per pair
    int wid = tid >> 5, lane = tid & 31;
    for (int p = 0; p < 32; p++) {
        int lp = wid * 32 + p;
        int gw = gw0 + lp;
        if (gw >= NPAIRS) break;
        int node = gw >> 2;
        int head = gw & 3;
        float acc = 0.f;
        #pragma unroll
        for (int r = 0; r < TOPK; r++) {
            float a = salpha[lp][r];
            int   c = scol[lp][r];
            acc += a * __ldg(&g_h[c * 128 + head * OUT_CH + lane]);
        }
        out[node * 128 + head * OUT_CH + lane] = (acc > 0.f) ? acc : expm1f(acc);
    }
}

// ---------------- launch (slot 3 = k_scores for ncu) ------------------------
extern "C" void kernel_launch(void* const* d_in, const int* in_sizes, int n_in,
                              void* d_out, int out_size) {
    const float* x   = (const float*)d_in[0];
    const float* W   = (const float*)d_in[1];
    const float* att = (const float*)d_in[2];
    const int*   ei  = (const int*)d_in[3];
    float* out = (float*)d_out;

    k_prep<<<64, 256>>>(W, att);                                    // 0
    k_hist<<<(N_EDGES / 4 + 255) / 256, 256>>>(ei);                 // 1
    k_scan1<<<NB_SCAN, 1024>>>();                                   // 2
    k_scores<<<(N_NODES * 32 + 255) / 256, 256>>>(x);               // 3 (profiled)
    k_gemm<<<(N_NODES + 127) / 128, 256>>>(x);                      // 4
    k_scan3<<<NB_SCAN, 1024>>>();                                   // 5
    k_scatter<<<(ET + 255) / 256, 256>>>(ei);                       // 6
    k_topkagg<<<(NPAIRS + 255) / 256, 256>>>(out);                  // 7
}